// round 2
// baseline (speedup 1.0000x reference)
#include <cuda_runtime.h>
#include <cuda_bf16.h>
#include <math.h>

// Problem constants
#define NM 1024
#define NH 16
#define ND 64
#define BATCH 4
#define SEQ 1024
#define ROWS (BATCH*SEQ)   // 4096

// ---------------------------------------------------------------------------
// Scratch (device globals; no allocation allowed)
// ---------------------------------------------------------------------------
__device__ float g_q[ROWS * NM];
__device__ float g_k[ROWS * NM];
__device__ float g_v[ROWS * NM];
__device__ float g_ctx[ROWS * NM];

// ---------------------------------------------------------------------------
// NT GEMM with bias: C[m][n] = sum_k A[m][k]*W[n][k] + bias[n]
// A: [M,K] row-major, W: [N,K] row-major. Tiles 128x128, BK=16, 8x8 microtile.
// M=4096, N=K=1024 (all divisible, no guards).
// ---------------------------------------------------------------------------
#define BM 128
#define BN 128
#define BK 16

__global__ __launch_bounds__(256, 2)
void gemm_nt_bias(const float* __restrict__ A,
                  const float* __restrict__ W,
                  const float* __restrict__ bias,
                  float* __restrict__ C,
                  int M, int N, int K)
{
    __shared__ float As[BK][BM];
    __shared__ float Ws[BK][BN];

    const int tid = threadIdx.x;
    const int tx = tid & 15;        // 0..15
    const int ty = tid >> 4;        // 0..15
    const int m0 = blockIdx.y * BM;
    const int n0 = blockIdx.x * BN;

    float acc[8][8];
#pragma unroll
    for (int i = 0; i < 8; i++)
#pragma unroll
        for (int j = 0; j < 8; j++) acc[i][j] = 0.0f;

    for (int kc = 0; kc < K; kc += BK) {
        // Load A tile and W tile (2048 floats each = 512 float4; 2 per thread per array)
#pragma unroll
        for (int s = 0; s < 2; s++) {
            int f   = tid + s * 256;      // float4 index 0..511
            int row = f >> 2;             // 0..127
            int k4  = (f & 3) << 2;       // 0,4,8,12
            float4 a = *(const float4*)(A + (size_t)(m0 + row) * K + kc + k4);
            As[k4 + 0][row] = a.x;
            As[k4 + 1][row] = a.y;
            As[k4 + 2][row] = a.z;
            As[k4 + 3][row] = a.w;
            float4 w = *(const float4*)(W + (size_t)(n0 + row) * K + kc + k4);
            Ws[k4 + 0][row] = w.x;
            Ws[k4 + 1][row] = w.y;
            Ws[k4 + 2][row] = w.z;
            Ws[k4 + 3][row] = w.w;
        }
        __syncthreads();

#pragma unroll
        for (int k = 0; k < BK; k++) {
            float4 a0 = *(const float4*)&As[k][ty * 8];
            float4 a1 = *(const float4*)&As[k][ty * 8 + 4];
            float4 b0 = *(const float4*)&Ws[k][tx * 8];
            float4 b1 = *(const float4*)&Ws[k][tx * 8 + 4];
            float av[8] = {a0.x, a0.y, a0.z, a0.w, a1.x, a1.y, a1.z, a1.w};
            float bv[8] = {b0.x, b0.y, b0.z, b0.w, b1.x, b1.y, b1.z, b1.w};
#pragma unroll
            for (int i = 0; i < 8; i++)
#pragma unroll
                for (int j = 0; j < 8; j++)
                    acc[i][j] = fmaf(av[i], bv[j], acc[i][j]);
        }
        __syncthreads();
    }

    // Epilogue: add bias, write C
#pragma unroll
    for (int i = 0; i < 8; i++) {
        int row = m0 + ty * 8 + i;
        float* cr = C + (size_t)row * N + n0 + tx * 8;
#pragma unroll
        for (int j = 0; j < 8; j++)
            cr[j] = acc[i][j] + bias[n0 + tx * 8 + j];
    }
}

// ---------------------------------------------------------------------------
// Flash-attention style masked softmax attention, per (b, h, 64-row q tile).
// q/k/v layout: [B, L, NM] with head h occupying columns h*64..h*64+63.
// scores = (q.k / 32) * m - (1-m)*1e9 ; softmax over k; ctx = attn @ v
// Block: 256 threads (16x16); each thread owns 4 rows x 4 cols of the tile.
// ---------------------------------------------------------------------------
#define TLD 65   // padded leading dim for 64-wide smem tiles

__global__ void attn_kernel(const float* __restrict__ q,
                            const float* __restrict__ k,
                            const float* __restrict__ v,
                            const int*   __restrict__ mask,
                            float* __restrict__ ctx)
{
    extern __shared__ float sm[];
    float* Qs = sm;                  // 64*TLD
    float* Ks = Qs + 64 * TLD;
    float* Vs = Ks + 64 * TLD;
    float* Ps = Vs + 64 * TLD;

    const int tid = threadIdx.x;
    const int tx = tid & 15;
    const int ty = tid >> 4;
    const int q0 = blockIdx.x * 64;
    const int h  = blockIdx.y;
    const int b  = blockIdx.z;

    const size_t base = (size_t)b * SEQ * NM + (size_t)h * ND;
    const size_t mbase = (size_t)b * SEQ * SEQ;

    // Load Q tile (stays resident)
    for (int idx = tid; idx < 64 * 64; idx += 256) {
        int r = idx >> 6, d = idx & 63;
        Qs[r * TLD + d] = q[base + (size_t)(q0 + r) * NM + d];
    }
    __syncthreads();

    float mr[4], lr[4], oacc[4][4];
#pragma unroll
    for (int i = 0; i < 4; i++) {
        mr[i] = -INFINITY;
        lr[i] = 0.0f;
#pragma unroll
        for (int j = 0; j < 4; j++) oacc[i][j] = 0.0f;
    }

    const float SCALE = 0.03125f;  // 1/sqrt(1024)

    for (int t = 0; t < 16; t++) {
        const int k0 = t * 64;
        // Load K and V tiles
        for (int idx = tid; idx < 64 * 64; idx += 256) {
            int r = idx >> 6, d = idx & 63;
            size_t g = base + (size_t)(k0 + r) * NM + d;
            Ks[r * TLD + d] = k[g];
            Vs[r * TLD + d] = v[g];
        }
        __syncthreads();

        // S = Q K^T (4x4 per thread)
        float s[4][4];
#pragma unroll
        for (int i = 0; i < 4; i++)
#pragma unroll
            for (int j = 0; j < 4; j++) s[i][j] = 0.0f;

        for (int kk = 0; kk < 64; kk++) {
            float qv[4], kv[4];
#pragma unroll
            for (int i = 0; i < 4; i++) qv[i] = Qs[(ty * 4 + i) * TLD + kk];
#pragma unroll
            for (int j = 0; j < 4; j++) kv[j] = Ks[(tx * 4 + j) * TLD + kk];
#pragma unroll
            for (int i = 0; i < 4; i++)
#pragma unroll
                for (int j = 0; j < 4; j++)
                    s[i][j] = fmaf(qv[i], kv[j], s[i][j]);
        }

        // Scale + mask + rowmax
        float rowmax[4];
#pragma unroll
        for (int i = 0; i < 4; i++) {
            const int qg = q0 + ty * 4 + i;
            const int* mrow = mask + mbase + (size_t)qg * SEQ + k0 + tx * 4;
            rowmax[i] = -INFINITY;
#pragma unroll
            for (int j = 0; j < 4; j++) {
                float mm = (float)mrow[j];
                s[i][j] = s[i][j] * SCALE * mm - (1.0f - mm) * 1e9f;
                rowmax[i] = fmaxf(rowmax[i], s[i][j]);
            }
        }
        // reduce rowmax over the 16 lanes sharing each row
#pragma unroll
        for (int off = 1; off < 16; off <<= 1)
#pragma unroll
            for (int i = 0; i < 4; i++)
                rowmax[i] = fmaxf(rowmax[i],
                                  __shfl_xor_sync(0xffffffffu, rowmax[i], off));

        // Online softmax update
#pragma unroll
        for (int i = 0; i < 4; i++) {
            float mnew = fmaxf(mr[i], rowmax[i]);
            float corr = __expf(mr[i] - mnew);
            mr[i] = mnew;
            lr[i] *= corr;
#pragma unroll
            for (int j = 0; j < 4; j++) oacc[i][j] *= corr;
            float rsum = 0.0f;
#pragma unroll
            for (int j = 0; j < 4; j++) {
                s[i][j] = __expf(s[i][j] - mnew);
                rsum += s[i][j];
            }
#pragma unroll
            for (int off = 1; off < 16; off <<= 1)
                rsum += __shfl_xor_sync(0xffffffffu, rsum, off);
            lr[i] += rsum;
        }

        // Write P to smem
#pragma unroll
        for (int i = 0; i < 4; i++)
#pragma unroll
            for (int j = 0; j < 4; j++)
                Ps[(ty * 4 + i) * TLD + tx * 4 + j] = s[i][j];
        __syncthreads();

        // O += P @ V
        for (int kk = 0; kk < 64; kk++) {
            float pv[4], vv[4];
#pragma unroll
            for (int i = 0; i < 4; i++) pv[i] = Ps[(ty * 4 + i) * TLD + kk];
#pragma unroll
            for (int j = 0; j < 4; j++) vv[j] = Vs[kk * TLD + tx * 4 + j];
#pragma unroll
            for (int i = 0; i < 4; i++)
#pragma unroll
                for (int j = 0; j < 4; j++)
                    oacc[i][j] = fmaf(pv[i], vv[j], oacc[i][j]);
        }
        __syncthreads();   // before next K/V overwrite
    }

    // Normalize and write ctx
#pragma unroll
    for (int i = 0; i < 4; i++) {
        float inv = 1.0f / lr[i];
        int row = q0 + ty * 4 + i;
        float* cr = ctx + base + (size_t)row * NM + tx * 4;
#pragma unroll
        for (int j = 0; j < 4; j++) cr[j] = oacc[i][j] * inv;
    }
}

// ---------------------------------------------------------------------------
// kernel_launch
// Inputs (metadata order): x, mask, Wq, bq, Wk, bk, Wv, bv, Wo, bo
// ---------------------------------------------------------------------------
extern "C" void kernel_launch(void* const* d_in, const int* in_sizes, int n_in,
                              void* d_out, int out_size)
{
    const float* x    = (const float*)d_in[0];
    const int*   mask = (const int*)  d_in[1];
    const float* Wq   = (const float*)d_in[2];
    const float* bq   = (const float*)d_in[3];
    const float* Wk   = (const float*)d_in[4];
    const float* bk   = (const float*)d_in[5];
    const float* Wv   = (const float*)d_in[6];
    const float* bv   = (const float*)d_in[7];
    const float* Wo   = (const float*)d_in[8];
    const float* bo   = (const float*)d_in[9];
    float* out = (float*)d_out;

    float *qp, *kp, *vp, *cp;
    cudaGetSymbolAddress((void**)&qp, g_q);
    cudaGetSymbolAddress((void**)&kp, g_k);
    cudaGetSymbolAddress((void**)&vp, g_v);
    cudaGetSymbolAddress((void**)&cp, g_ctx);

    dim3 gblock(256);
    dim3 ggrid(NM / BN, ROWS / BM);   // (8, 32)

    gemm_nt_bias<<<ggrid, gblock>>>(x, Wq, bq, qp, ROWS, NM, NM);
    gemm_nt_bias<<<ggrid, gblock>>>(x, Wk, bk, kp, ROWS, NM, NM);
    gemm_nt_bias<<<ggrid, gblock>>>(x, Wv, bv, vp, ROWS, NM, NM);

    const int smem = 4 * 64 * TLD * sizeof(float);   // ~66.6 KB
    cudaFuncSetAttribute(attn_kernel,
                         cudaFuncAttributeMaxDynamicSharedMemorySize, smem);
    dim3 agrid(SEQ / 64, NH, BATCH);  // (16,16,4)
    attn_kernel<<<agrid, 256, smem>>>(qp, kp, vp, mask, cp);

    gemm_nt_bias<<<ggrid, gblock>>>(cp, Wo, bo, out, ROWS, NM, NM);
}

// round 4
// speedup vs baseline: 1.3931x; 1.3931x over previous
#include <cuda_runtime.h>
#include <cuda_bf16.h>
#include <math.h>
#include <stdint.h>

// Problem constants
#define NM 1024
#define NH 16
#define ND 64
#define BATCH 4
#define SEQ 1024
#define ROWS (BATCH*SEQ)   // 4096

// ---------------------------------------------------------------------------
// Scratch (device globals; no allocation allowed)
// ---------------------------------------------------------------------------
__device__ float g_q[ROWS * NM];
__device__ float g_k[ROWS * NM];
__device__ float g_v[ROWS * NM];
__device__ float g_ctx[ROWS * NM];

// ===========================================================================
// Helpers
// ===========================================================================
__device__ __forceinline__ uint32_t smem_u32(const void* p) {
    uint32_t a;
    asm("{ .reg .u64 t; cvta.to.shared.u64 t, %1; cvt.u32.u64 %0, t; }"
        : "=r"(a) : "l"(p));
    return a;
}

__device__ __forceinline__ void ldm_x4(uint32_t* r, uint32_t a) {
    asm volatile("ldmatrix.sync.aligned.m8n8.x4.shared.b16 {%0,%1,%2,%3}, [%4];"
                 : "=r"(r[0]), "=r"(r[1]), "=r"(r[2]), "=r"(r[3]) : "r"(a));
}
__device__ __forceinline__ void ldm_x2(uint32_t* r, uint32_t a) {
    asm volatile("ldmatrix.sync.aligned.m8n8.x2.shared.b16 {%0,%1}, [%2];"
                 : "=r"(r[0]), "=r"(r[1]) : "r"(a));
}
__device__ __forceinline__ void mma_bf16(float* c, const uint32_t* a,
                                         const uint32_t* b) {
    asm volatile(
        "mma.sync.aligned.m16n8k16.row.col.f32.bf16.bf16.f32 "
        "{%0,%1,%2,%3}, {%4,%5,%6,%7}, {%8,%9}, {%0,%1,%2,%3};"
        : "+f"(c[0]), "+f"(c[1]), "+f"(c[2]), "+f"(c[3])
        : "r"(a[0]), "r"(a[1]), "r"(a[2]), "r"(a[3]), "r"(b[0]), "r"(b[1]));
}

// split fp32 pair -> bf16x2 hi + bf16x2 lo residual
__device__ __forceinline__ void split2(float x, float y, uint32_t& hi, uint32_t& lo) {
    __nv_bfloat162 h = __floats2bfloat162_rn(x, y);
    float2 hf = __bfloat1622float2(h);
    __nv_bfloat162 l = __floats2bfloat162_rn(x - hf.x, y - hf.y);
    hi = reinterpret_cast<uint32_t&>(h);
    lo = reinterpret_cast<uint32_t&>(l);
}

// ===========================================================================
// bf16-split GEMM via mma.sync: C[m][n] = sum_k A[m][k]*W[n][k] + bias[n]
// CTA 128x128, BK=32, 8 warps (2x4), each warp 64x32 (4x4 m16n8k16 tiles).
// M=4096, N=K=1024 hardcoded.
// ===========================================================================
#define BKP 40   // padded K stride in bf16 elems (80 bytes)

__global__ __launch_bounds__(256)
void gemm_mma(const float* __restrict__ A, const float* __restrict__ W,
              const float* __restrict__ bias, float* __restrict__ C)
{
    __shared__ __nv_bfloat16 Ah[128 * BKP], Al[128 * BKP];
    __shared__ __nv_bfloat16 Bh[128 * BKP], Bl[128 * BKP];

    const int tid  = threadIdx.x;
    const int lane = tid & 31;
    const int wid  = tid >> 5;
    const int wm   = (wid >> 2) * 64;   // warp row offset within tile
    const int wn   = (wid & 3) * 32;    // warp col offset within tile
    const int m0   = blockIdx.y * 128;
    const int n0   = blockIdx.x * 128;

    const uint32_t sAh = smem_u32(Ah), sAl = smem_u32(Al);
    const uint32_t sBh = smem_u32(Bh), sBl = smem_u32(Bl);

    // ldmatrix per-lane base offsets (bytes)
    const uint32_t a_off = ((wm + (lane & 15)) * BKP + (lane >> 4) * 8) * 2;
    const uint32_t b_off = ((wn + (lane & 7)) * BKP + ((lane >> 3) & 1) * 8) * 2;

    float acc[4][4][4];
#pragma unroll
    for (int i = 0; i < 4; i++)
#pragma unroll
        for (int j = 0; j < 4; j++)
#pragma unroll
            for (int r = 0; r < 4; r++) acc[i][j][r] = 0.0f;

    for (int kc = 0; kc < 1024; kc += 32) {
        // Load + convert A[128x32], W[128x32] fp32 -> bf16 hi/lo in smem
#pragma unroll
        for (int s = 0; s < 4; s++) {
            int f  = tid + s * 256;     // float4 idx 0..1023
            int r  = f >> 3;            // row 0..127
            int c4 = (f & 7) << 2;      // col 0,4,..,28

            float4 a = *(const float4*)(A + (size_t)(m0 + r) * 1024 + kc + c4);
            uint2 h, l;
            split2(a.x, a.y, h.x, l.x);
            split2(a.z, a.w, h.y, l.y);
            *(uint2*)&Ah[r * BKP + c4] = h;
            *(uint2*)&Al[r * BKP + c4] = l;

            float4 w = *(const float4*)(W + (size_t)(n0 + r) * 1024 + kc + c4);
            split2(w.x, w.y, h.x, l.x);
            split2(w.z, w.w, h.y, l.y);
            *(uint2*)&Bh[r * BKP + c4] = h;
            *(uint2*)&Bl[r * BKP + c4] = l;
        }
        __syncthreads();

#pragma unroll
        for (int ks = 0; ks < 2; ks++) {          // two k16 steps
            const uint32_t kb = ks * 16 * 2;      // byte offset along K

            uint32_t ahf[4][4], alf[4][4];
#pragma unroll
            for (int tm = 0; tm < 4; tm++) {
                uint32_t o = a_off + kb + tm * (16 * BKP * 2);
                ldm_x4(ahf[tm], sAh + o);
                ldm_x4(alf[tm], sAl + o);
            }

            uint32_t bf[4][2];
#pragma unroll
            for (int tn = 0; tn < 4; tn++)
                ldm_x2(bf[tn], sBh + b_off + kb + tn * (8 * BKP * 2));
#pragma unroll
            for (int tm = 0; tm < 4; tm++)
#pragma unroll
                for (int tn = 0; tn < 4; tn++) {
                    mma_bf16(acc[tm][tn], ahf[tm], bf[tn]);   // hi*hi
                }
#pragma unroll
            for (int tm = 0; tm < 4; tm++)
#pragma unroll
                for (int tn = 0; tn < 4; tn++)
                    mma_bf16(acc[tm][tn], alf[tm], bf[tn]);   // lo*hi

#pragma unroll
            for (int tn = 0; tn < 4; tn++)
                ldm_x2(bf[tn], sBl + b_off + kb + tn * (8 * BKP * 2));
#pragma unroll
            for (int tm = 0; tm < 4; tm++)
#pragma unroll
                for (int tn = 0; tn < 4; tn++)
                    mma_bf16(acc[tm][tn], ahf[tm], bf[tn]);   // hi*lo
        }
        __syncthreads();
    }

    // Epilogue: add bias, store
    const int qr = lane >> 2;          // 0..7
    const int qc = (lane & 3) * 2;     // 0,2,4,6
#pragma unroll
    for (int tm = 0; tm < 4; tm++) {
        int row = m0 + wm + tm * 16 + qr;
#pragma unroll
        for (int tn = 0; tn < 4; tn++) {
            int col = n0 + wn + tn * 8 + qc;
            float b0 = bias[col], b1 = bias[col + 1];
            float2* p0 = (float2*)(C + (size_t)row * 1024 + col);
            float2* p1 = (float2*)(C + (size_t)(row + 8) * 1024 + col);
            *p0 = make_float2(acc[tm][tn][0] + b0, acc[tm][tn][1] + b1);
            *p1 = make_float2(acc[tm][tn][2] + b0, acc[tm][tn][3] + b1);
        }
    }
}

// ---------------------------------------------------------------------------
// Flash-attention style masked softmax attention (unchanged)
// ---------------------------------------------------------------------------
#define TLD 65

__global__ void attn_kernel(const float* __restrict__ q,
                            const float* __restrict__ k,
                            const float* __restrict__ v,
                            const int*   __restrict__ mask,
                            float* __restrict__ ctx)
{
    extern __shared__ float sm[];
    float* Qs = sm;
    float* Ks = Qs + 64 * TLD;
    float* Vs = Ks + 64 * TLD;
    float* Ps = Vs + 64 * TLD;

    const int tid = threadIdx.x;
    const int tx = tid & 15;
    const int ty = tid >> 4;
    const int q0 = blockIdx.x * 64;
    const int h  = blockIdx.y;
    const int b  = blockIdx.z;

    const size_t base = (size_t)b * SEQ * NM + (size_t)h * ND;
    const size_t mbase = (size_t)b * SEQ * SEQ;

    for (int idx = tid; idx < 64 * 64; idx += 256) {
        int r = idx >> 6, d = idx & 63;
        Qs[r * TLD + d] = q[base + (size_t)(q0 + r) * NM + d];
    }
    __syncthreads();

    float mr[4], lr[4], oacc[4][4];
#pragma unroll
    for (int i = 0; i < 4; i++) {
        mr[i] = -INFINITY;
        lr[i] = 0.0f;
#pragma unroll
        for (int j = 0; j < 4; j++) oacc[i][j] = 0.0f;
    }

    const float SCALE = 0.03125f;

    for (int t = 0; t < 16; t++) {
        const int k0 = t * 64;
        for (int idx = tid; idx < 64 * 64; idx += 256) {
            int r = idx >> 6, d = idx & 63;
            size_t g = base + (size_t)(k0 + r) * NM + d;
            Ks[r * TLD + d] = k[g];
            Vs[r * TLD + d] = v[g];
        }
        __syncthreads();

        float s[4][4];
#pragma unroll
        for (int i = 0; i < 4; i++)
#pragma unroll
            for (int j = 0; j < 4; j++) s[i][j] = 0.0f;

        for (int kk = 0; kk < 64; kk++) {
            float qv[4], kv[4];
#pragma unroll
            for (int i = 0; i < 4; i++) qv[i] = Qs[(ty * 4 + i) * TLD + kk];
#pragma unroll
            for (int j = 0; j < 4; j++) kv[j] = Ks[(tx * 4 + j) * TLD + kk];
#pragma unroll
            for (int i = 0; i < 4; i++)
#pragma unroll
                for (int j = 0; j < 4; j++)
                    s[i][j] = fmaf(qv[i], kv[j], s[i][j]);
        }

        float rowmax[4];
#pragma unroll
        for (int i = 0; i < 4; i++) {
            const int qg = q0 + ty * 4 + i;
            const int* mrow = mask + mbase + (size_t)qg * SEQ + k0 + tx * 4;
            rowmax[i] = -INFINITY;
#pragma unroll
            for (int j = 0; j < 4; j++) {
                float mm = (float)mrow[j];
                s[i][j] = s[i][j] * SCALE * mm - (1.0f - mm) * 1e9f;
                rowmax[i] = fmaxf(rowmax[i], s[i][j]);
            }
        }
#pragma unroll
        for (int off = 1; off < 16; off <<= 1)
#pragma unroll
            for (int i = 0; i < 4; i++)
                rowmax[i] = fmaxf(rowmax[i],
                                  __shfl_xor_sync(0xffffffffu, rowmax[i], off));

#pragma unroll
        for (int i = 0; i < 4; i++) {
            float mnew = fmaxf(mr[i], rowmax[i]);
            float corr = __expf(mr[i] - mnew);
            mr[i] = mnew;
            lr[i] *= corr;
#pragma unroll
            for (int j = 0; j < 4; j++) oacc[i][j] *= corr;
            float rsum = 0.0f;
#pragma unroll
            for (int j = 0; j < 4; j++) {
                s[i][j] = __expf(s[i][j] - mnew);
                rsum += s[i][j];
            }
#pragma unroll
            for (int off = 1; off < 16; off <<= 1)
                rsum += __shfl_xor_sync(0xffffffffu, rsum, off);
            lr[i] += rsum;
        }

#pragma unroll
        for (int i = 0; i < 4; i++)
#pragma unroll
            for (int j = 0; j < 4; j++)
                Ps[(ty * 4 + i) * TLD + tx * 4 + j] = s[i][j];
        __syncthreads();

        for (int kk = 0; kk < 64; kk++) {
            float pv[4], vv[4];
#pragma unroll
            for (int i = 0; i < 4; i++) pv[i] = Ps[(ty * 4 + i) * TLD + kk];
#pragma unroll
            for (int j = 0; j < 4; j++) vv[j] = Vs[kk * TLD + tx * 4 + j];
#pragma unroll
            for (int i = 0; i < 4; i++)
#pragma unroll
                for (int j = 0; j < 4; j++)
                    oacc[i][j] = fmaf(pv[i], vv[j], oacc[i][j]);
        }
        __syncthreads();
    }

#pragma unroll
    for (int i = 0; i < 4; i++) {
        float inv = 1.0f / lr[i];
        int row = q0 + ty * 4 + i;
        float* cr = ctx + base + (size_t)row * NM + tx * 4;
#pragma unroll
        for (int j = 0; j < 4; j++) cr[j] = oacc[i][j] * inv;
    }
}

// ---------------------------------------------------------------------------
// kernel_launch — inputs: x, mask, Wq, bq, Wk, bk, Wv, bv, Wo, bo
// ---------------------------------------------------------------------------
extern "C" void kernel_launch(void* const* d_in, const int* in_sizes, int n_in,
                              void* d_out, int out_size)
{
    const float* x    = (const float*)d_in[0];
    const int*   mask = (const int*)  d_in[1];
    const float* Wq   = (const float*)d_in[2];
    const float* bq   = (const float*)d_in[3];
    const float* Wk   = (const float*)d_in[4];
    const float* bk   = (const float*)d_in[5];
    const float* Wv   = (const float*)d_in[6];
    const float* bv   = (const float*)d_in[7];
    const float* Wo   = (const float*)d_in[8];
    const float* bo   = (const float*)d_in[9];
    float* out = (float*)d_out;

    float *qp, *kp, *vp, *cp;
    cudaGetSymbolAddress((void**)&qp, g_q);
    cudaGetSymbolAddress((void**)&kp, g_k);
    cudaGetSymbolAddress((void**)&vp, g_v);
    cudaGetSymbolAddress((void**)&cp, g_ctx);

    dim3 gblock(256);
    dim3 ggrid(NM / 128, ROWS / 128);   // (8, 32)

    gemm_mma<<<ggrid, gblock>>>(x, Wq, bq, qp);
    gemm_mma<<<ggrid, gblock>>>(x, Wk, bk, kp);
    gemm_mma<<<ggrid, gblock>>>(x, Wv, bv, vp);

    const int smem = 4 * 64 * TLD * sizeof(float);
    cudaFuncSetAttribute(attn_kernel,
                         cudaFuncAttributeMaxDynamicSharedMemorySize, smem);
    dim3 agrid(SEQ / 64, NH, BATCH);
    attn_kernel<<<agrid, 256, smem>>>(qp, kp, vp, mask, cp);

    gemm_mma<<<ggrid, gblock>>>(cp, Wo, bo, out);
}

// round 5
// speedup vs baseline: 2.1537x; 1.5460x over previous
#include <cuda_runtime.h>
#include <cuda_bf16.h>
#include <math.h>
#include <stdint.h>

// Problem constants
#define NM 1024
#define NH 16
#define ND 64
#define BATCH 4
#define SEQ 1024
#define ROWS (BATCH*SEQ)   // 4096

// ---------------------------------------------------------------------------
// Scratch (device globals; no allocation allowed)
// ---------------------------------------------------------------------------
__device__ float g_q[ROWS * NM];
__device__ float g_k[ROWS * NM];
__device__ float g_v[ROWS * NM];
__device__ float g_ctx[ROWS * NM];

// ===========================================================================
// Helpers
// ===========================================================================
__device__ __forceinline__ uint32_t smem_u32(const void* p) {
    uint32_t a;
    asm("{ .reg .u64 t; cvta.to.shared.u64 t, %1; cvt.u32.u64 %0, t; }"
        : "=r"(a) : "l"(p));
    return a;
}

__device__ __forceinline__ void ldm_x4(uint32_t* r, uint32_t a) {
    asm volatile("ldmatrix.sync.aligned.m8n8.x4.shared.b16 {%0,%1,%2,%3}, [%4];"
                 : "=r"(r[0]), "=r"(r[1]), "=r"(r[2]), "=r"(r[3]) : "r"(a));
}
__device__ __forceinline__ void ldm_x4t(uint32_t* r, uint32_t a) {
    asm volatile("ldmatrix.sync.aligned.m8n8.x4.trans.shared.b16 {%0,%1,%2,%3}, [%4];"
                 : "=r"(r[0]), "=r"(r[1]), "=r"(r[2]), "=r"(r[3]) : "r"(a));
}
__device__ __forceinline__ void ldm_x2(uint32_t* r, uint32_t a) {
    asm volatile("ldmatrix.sync.aligned.m8n8.x2.shared.b16 {%0,%1}, [%2];"
                 : "=r"(r[0]), "=r"(r[1]) : "r"(a));
}
__device__ __forceinline__ void mma_bf16(float* c, const uint32_t* a,
                                         const uint32_t* b) {
    asm volatile(
        "mma.sync.aligned.m16n8k16.row.col.f32.bf16.bf16.f32 "
        "{%0,%1,%2,%3}, {%4,%5,%6,%7}, {%8,%9}, {%0,%1,%2,%3};"
        : "+f"(c[0]), "+f"(c[1]), "+f"(c[2]), "+f"(c[3])
        : "r"(a[0]), "r"(a[1]), "r"(a[2]), "r"(a[3]), "r"(b[0]), "r"(b[1]));
}

// split fp32 pair -> bf16x2 hi + bf16x2 lo residual
__device__ __forceinline__ void split2(float x, float y, uint32_t& hi, uint32_t& lo) {
    __nv_bfloat162 h = __floats2bfloat162_rn(x, y);
    float2 hf = __bfloat1622float2(h);
    __nv_bfloat162 l = __floats2bfloat162_rn(x - hf.x, y - hf.y);
    hi = reinterpret_cast<uint32_t&>(h);
    lo = reinterpret_cast<uint32_t&>(l);
}

// ===========================================================================
// bf16-split GEMM via mma.sync (unchanged from R3)
// ===========================================================================
#define BKP 40   // padded K stride in bf16 elems

__global__ __launch_bounds__(256)
void gemm_mma(const float* __restrict__ A, const float* __restrict__ W,
              const float* __restrict__ bias, float* __restrict__ C)
{
    __shared__ __nv_bfloat16 Ah[128 * BKP], Al[128 * BKP];
    __shared__ __nv_bfloat16 Bh[128 * BKP], Bl[128 * BKP];

    const int tid  = threadIdx.x;
    const int lane = tid & 31;
    const int wid  = tid >> 5;
    const int wm   = (wid >> 2) * 64;
    const int wn   = (wid & 3) * 32;
    const int m0   = blockIdx.y * 128;
    const int n0   = blockIdx.x * 128;

    const uint32_t sAh = smem_u32(Ah), sAl = smem_u32(Al);
    const uint32_t sBh = smem_u32(Bh), sBl = smem_u32(Bl);

    const uint32_t a_off = ((wm + (lane & 15)) * BKP + (lane >> 4) * 8) * 2;
    const uint32_t b_off = ((wn + (lane & 7)) * BKP + ((lane >> 3) & 1) * 8) * 2;

    float acc[4][4][4];
#pragma unroll
    for (int i = 0; i < 4; i++)
#pragma unroll
        for (int j = 0; j < 4; j++)
#pragma unroll
            for (int r = 0; r < 4; r++) acc[i][j][r] = 0.0f;

    for (int kc = 0; kc < 1024; kc += 32) {
#pragma unroll
        for (int s = 0; s < 4; s++) {
            int f  = tid + s * 256;
            int r  = f >> 3;
            int c4 = (f & 7) << 2;

            float4 a = *(const float4*)(A + (size_t)(m0 + r) * 1024 + kc + c4);
            uint2 h, l;
            split2(a.x, a.y, h.x, l.x);
            split2(a.z, a.w, h.y, l.y);
            *(uint2*)&Ah[r * BKP + c4] = h;
            *(uint2*)&Al[r * BKP + c4] = l;

            float4 w = *(const float4*)(W + (size_t)(n0 + r) * 1024 + kc + c4);
            split2(w.x, w.y, h.x, l.x);
            split2(w.z, w.w, h.y, l.y);
            *(uint2*)&Bh[r * BKP + c4] = h;
            *(uint2*)&Bl[r * BKP + c4] = l;
        }
        __syncthreads();

#pragma unroll
        for (int ks = 0; ks < 2; ks++) {
            const uint32_t kb = ks * 16 * 2;

            uint32_t ahf[4][4], alf[4][4];
#pragma unroll
            for (int tm = 0; tm < 4; tm++) {
                uint32_t o = a_off + kb + tm * (16 * BKP * 2);
                ldm_x4(ahf[tm], sAh + o);
                ldm_x4(alf[tm], sAl + o);
            }

            uint32_t bf[4][2];
#pragma unroll
            for (int tn = 0; tn < 4; tn++)
                ldm_x2(bf[tn], sBh + b_off + kb + tn * (8 * BKP * 2));
#pragma unroll
            for (int tm = 0; tm < 4; tm++)
#pragma unroll
                for (int tn = 0; tn < 4; tn++)
                    mma_bf16(acc[tm][tn], ahf[tm], bf[tn]);
#pragma unroll
            for (int tm = 0; tm < 4; tm++)
#pragma unroll
                for (int tn = 0; tn < 4; tn++)
                    mma_bf16(acc[tm][tn], alf[tm], bf[tn]);

#pragma unroll
            for (int tn = 0; tn < 4; tn++)
                ldm_x2(bf[tn], sBl + b_off + kb + tn * (8 * BKP * 2));
#pragma unroll
            for (int tm = 0; tm < 4; tm++)
#pragma unroll
                for (int tn = 0; tn < 4; tn++)
                    mma_bf16(acc[tm][tn], ahf[tm], bf[tn]);
        }
        __syncthreads();
    }

    const int qr = lane >> 2;
    const int qc = (lane & 3) * 2;
#pragma unroll
    for (int tm = 0; tm < 4; tm++) {
        int row = m0 + wm + tm * 16 + qr;
#pragma unroll
        for (int tn = 0; tn < 4; tn++) {
            int col = n0 + wn + tn * 8 + qc;
            float b0 = bias[col], b1 = bias[col + 1];
            float2* p0 = (float2*)(C + (size_t)row * 1024 + col);
            float2* p1 = (float2*)(C + (size_t)(row + 8) * 1024 + col);
            *p0 = make_float2(acc[tm][tn][0] + b0, acc[tm][tn][1] + b1);
            *p1 = make_float2(acc[tm][tn][2] + b0, acc[tm][tn][3] + b1);
        }
    }
}

// ===========================================================================
// Tensor-core flash attention. CTA: 128 q-rows x one head. 8 warps x 16 rows.
// S = Q K^T with bf16 hi/lo split; online softmax; O = P V with P/V split.
// ===========================================================================
#define ALD 72   // padded smem stride (bf16 elems)

__global__ __launch_bounds__(256)
void attn_mma(const float* __restrict__ q, const float* __restrict__ k,
              const float* __restrict__ v, const int* __restrict__ mask,
              float* __restrict__ ctx)
{
    extern __shared__ __nv_bfloat16 smx[];
    __nv_bfloat16* Qh = smx;
    __nv_bfloat16* Ql = Qh + 128 * ALD;
    __nv_bfloat16* Kh = Ql + 128 * ALD;
    __nv_bfloat16* Kl = Kh + 128 * ALD;
    __nv_bfloat16* Vh = Kl + 128 * ALD;
    __nv_bfloat16* Vl = Vh + 128 * ALD;

    const int tid  = threadIdx.x;
    const int lane = tid & 31;
    const int wid  = tid >> 5;
    const int q0   = blockIdx.x * 128;
    const int h    = blockIdx.y;
    const int b    = blockIdx.z;

    const size_t base  = (size_t)b * SEQ * NM + (size_t)h * ND;
    const size_t mbase = (size_t)b * SEQ * SEQ;

    const uint32_t sQh = smem_u32(Qh), sQl = smem_u32(Ql);
    const uint32_t sKh = smem_u32(Kh), sKl = smem_u32(Kl);
    const uint32_t sVh = smem_u32(Vh), sVl = smem_u32(Vl);

    // ---- Load + split Q tile (128x64) ----
#pragma unroll
    for (int s = 0; s < 8; s++) {
        int f  = tid + s * 256;       // float4 idx 0..2047
        int r  = f >> 4;              // row
        int c4 = (f & 15) << 2;       // col 0..60
        float4 a = *(const float4*)(q + base + (size_t)(q0 + r) * NM + c4);
        uint2 hh, ll;
        split2(a.x, a.y, hh.x, ll.x);
        split2(a.z, a.w, hh.y, ll.y);
        *(uint2*)&Qh[r * ALD + c4] = hh;
        *(uint2*)&Ql[r * ALD + c4] = ll;
    }
    __syncthreads();

    // ---- Persistent Q fragments (warp rows wid*16..wid*16+15) ----
    uint32_t qfh[4][4], qfl[4][4];
    {
        uint32_t qo = ((wid * 16 + (lane & 15)) * ALD + (lane >> 4) * 8) * 2;
#pragma unroll
        for (int ks = 0; ks < 4; ks++) {
            ldm_x4(qfh[ks], sQh + qo + ks * 32);
            ldm_x4(qfl[ks], sQl + qo + ks * 32);
        }
    }

    float oacc[8][4];
#pragma unroll
    for (int i = 0; i < 8; i++)
#pragma unroll
        for (int r = 0; r < 4; r++) oacc[i][r] = 0.0f;
    float mr1 = -INFINITY, mr2 = -INFINITY, lr1 = 0.0f, lr2 = 0.0f;

    const float SCALE = 0.03125f;
    const int r1 = wid * 16 + (lane >> 2);

    // ldmatrix per-lane offsets
    const uint32_t koff = ((lane & 7) * ALD + ((lane >> 3) & 3) * 8) * 2;
    const uint32_t voff = (((lane & 7) + 8 * ((lane >> 3) & 1)) * ALD) * 2
                        + ((lane >> 4) & 1) * 16;

    for (int t = 0; t < 8; t++) {
        const int k0 = t * 128;
        // ---- Load + split K, V tiles (128x64 each) ----
#pragma unroll
        for (int s = 0; s < 8; s++) {
            int f  = tid + s * 256;
            int r  = f >> 4;
            int c4 = (f & 15) << 2;
            size_t g = base + (size_t)(k0 + r) * NM + c4;
            float4 a = *(const float4*)(k + g);
            uint2 hh, ll;
            split2(a.x, a.y, hh.x, ll.x);
            split2(a.z, a.w, hh.y, ll.y);
            *(uint2*)&Kh[r * ALD + c4] = hh;
            *(uint2*)&Kl[r * ALD + c4] = ll;
            float4 w = *(const float4*)(v + g);
            split2(w.x, w.y, hh.x, ll.x);
            split2(w.z, w.w, hh.y, ll.y);
            *(uint2*)&Vh[r * ALD + c4] = hh;
            *(uint2*)&Vl[r * ALD + c4] = ll;
        }
        __syncthreads();

        // ---- S = Q K^T (warp: 16 x 128) ----
        float sacc[16][4];
#pragma unroll
        for (int j = 0; j < 16; j++) {
#pragma unroll
            for (int r = 0; r < 4; r++) sacc[j][r] = 0.0f;
            uint32_t ka = koff + (uint32_t)(j * 8 * ALD * 2);
            uint32_t khf[8], klf[8];
            ldm_x4(khf,     sKh + ka);
            ldm_x4(khf + 4, sKh + ka + 64);
            ldm_x4(klf,     sKl + ka);
            ldm_x4(klf + 4, sKl + ka + 64);
#pragma unroll
            for (int ks = 0; ks < 4; ks++) {
                mma_bf16(sacc[j], qfh[ks], &khf[ks * 2]);
                mma_bf16(sacc[j], qfl[ks], &khf[ks * 2]);
                mma_bf16(sacc[j], qfh[ks], &klf[ks * 2]);
            }
        }

        // ---- mask + scale + row max ----
        const int* mp = mask + mbase + (size_t)(q0 + r1) * SEQ + k0 + (lane & 3) * 2;
        float rmax1 = -INFINITY, rmax2 = -INFINITY;
#pragma unroll
        for (int j = 0; j < 16; j++) {
            int2 ma = *(const int2*)(mp + j * 8);
            int2 mb = *(const int2*)(mp + 8 * SEQ + j * 8);
            float m0f = (float)ma.x, m1f = (float)ma.y;
            float m2f = (float)mb.x, m3f = (float)mb.y;
            sacc[j][0] = sacc[j][0] * SCALE * m0f - (1.0f - m0f) * 1e9f;
            sacc[j][1] = sacc[j][1] * SCALE * m1f - (1.0f - m1f) * 1e9f;
            sacc[j][2] = sacc[j][2] * SCALE * m2f - (1.0f - m2f) * 1e9f;
            sacc[j][3] = sacc[j][3] * SCALE * m3f - (1.0f - m3f) * 1e9f;
            rmax1 = fmaxf(rmax1, fmaxf(sacc[j][0], sacc[j][1]));
            rmax2 = fmaxf(rmax2, fmaxf(sacc[j][2], sacc[j][3]));
        }
#pragma unroll
        for (int off = 1; off < 4; off <<= 1) {
            rmax1 = fmaxf(rmax1, __shfl_xor_sync(0xffffffffu, rmax1, off));
            rmax2 = fmaxf(rmax2, __shfl_xor_sync(0xffffffffu, rmax2, off));
        }

        // ---- online softmax update ----
        float mn1 = fmaxf(mr1, rmax1);
        float mn2 = fmaxf(mr2, rmax2);
        float c1 = __expf(mr1 - mn1);
        float c2 = __expf(mr2 - mn2);
        mr1 = mn1; mr2 = mn2;
#pragma unroll
        for (int i = 0; i < 8; i++) {
            oacc[i][0] *= c1; oacc[i][1] *= c1;
            oacc[i][2] *= c2; oacc[i][3] *= c2;
        }
        float rs1 = 0.0f, rs2 = 0.0f;
#pragma unroll
        for (int j = 0; j < 16; j++) {
            sacc[j][0] = __expf(sacc[j][0] - mn1);
            sacc[j][1] = __expf(sacc[j][1] - mn1);
            sacc[j][2] = __expf(sacc[j][2] - mn2);
            sacc[j][3] = __expf(sacc[j][3] - mn2);
            rs1 += sacc[j][0] + sacc[j][1];
            rs2 += sacc[j][2] + sacc[j][3];
        }
#pragma unroll
        for (int off = 1; off < 4; off <<= 1) {
            rs1 += __shfl_xor_sync(0xffffffffu, rs1, off);
            rs2 += __shfl_xor_sync(0xffffffffu, rs2, off);
        }
        lr1 = lr1 * c1 + rs1;
        lr2 = lr2 * c2 + rs2;

        // ---- O += P V ----
#pragma unroll
        for (int ks = 0; ks < 8; ks++) {
            // P fragments from S tiles (2ks, 2ks+1), hi + residual
            uint32_t ph[4], pl[4];
            split2(sacc[2*ks][0],   sacc[2*ks][1],   ph[0], pl[0]);
            split2(sacc[2*ks][2],   sacc[2*ks][3],   ph[1], pl[1]);
            split2(sacc[2*ks+1][0], sacc[2*ks+1][1], ph[2], pl[2]);
            split2(sacc[2*ks+1][2], sacc[2*ks+1][3], ph[3], pl[3]);

            uint32_t va = voff + (uint32_t)(ks * 16 * ALD * 2);
#pragma unroll
            for (int tp = 0; tp < 4; tp++) {
                uint32_t vh[4], vl[4];
                ldm_x4t(vh, sVh + va + tp * 32);
                ldm_x4t(vl, sVl + va + tp * 32);
                mma_bf16(oacc[2*tp],   ph, &vh[0]);
                mma_bf16(oacc[2*tp+1], ph, &vh[2]);
                mma_bf16(oacc[2*tp],   pl, &vh[0]);
                mma_bf16(oacc[2*tp+1], pl, &vh[2]);
                mma_bf16(oacc[2*tp],   ph, &vl[0]);
                mma_bf16(oacc[2*tp+1], ph, &vl[2]);
            }
        }
        __syncthreads();   // before K/V overwrite next iter
    }

    // ---- normalize + store ctx ----
    float i1 = 1.0f / lr1, i2 = 1.0f / lr2;
    float* c0 = ctx + base + (size_t)(q0 + r1) * NM + (lane & 3) * 2;
    float* c8 = c0 + 8 * NM;
#pragma unroll
    for (int tn = 0; tn < 8; tn++) {
        *(float2*)(c0 + tn * 8) = make_float2(oacc[tn][0] * i1, oacc[tn][1] * i1);
        *(float2*)(c8 + tn * 8) = make_float2(oacc[tn][2] * i2, oacc[tn][3] * i2);
    }
}

// ---------------------------------------------------------------------------
// kernel_launch — inputs: x, mask, Wq, bq, Wk, bk, Wv, bv, Wo, bo
// ---------------------------------------------------------------------------
extern "C" void kernel_launch(void* const* d_in, const int* in_sizes, int n_in,
                              void* d_out, int out_size)
{
    const float* x    = (const float*)d_in[0];
    const int*   mask = (const int*)  d_in[1];
    const float* Wq   = (const float*)d_in[2];
    const float* bq   = (const float*)d_in[3];
    const float* Wk   = (const float*)d_in[4];
    const float* bk   = (const float*)d_in[5];
    const float* Wv   = (const float*)d_in[6];
    const float* bv   = (const float*)d_in[7];
    const float* Wo   = (const float*)d_in[8];
    const float* bo   = (const float*)d_in[9];
    float* out = (float*)d_out;

    float *qp, *kp, *vp, *cp;
    cudaGetSymbolAddress((void**)&qp, g_q);
    cudaGetSymbolAddress((void**)&kp, g_k);
    cudaGetSymbolAddress((void**)&vp, g_v);
    cudaGetSymbolAddress((void**)&cp, g_ctx);

    dim3 gblock(256);
    dim3 ggrid(NM / 128, ROWS / 128);   // (8, 32)

    gemm_mma<<<ggrid, gblock>>>(x, Wq, bq, qp);
    gemm_mma<<<ggrid, gblock>>>(x, Wk, bk, kp);
    gemm_mma<<<ggrid, gblock>>>(x, Wv, bv, vp);

    const int asmem = 6 * 128 * ALD * sizeof(__nv_bfloat16);  // 110592
    cudaFuncSetAttribute(attn_mma,
                         cudaFuncAttributeMaxDynamicSharedMemorySize, asmem);
    dim3 agrid(SEQ / 128, NH, BATCH);   // (8,16,4)
    attn_mma<<<agrid, 256, asmem>>>(qp, kp, vp, mask, cp);

    gemm_mma<<<ggrid, gblock>>>(cp, Wo, bo, out);
}

// round 6
// speedup vs baseline: 2.7802x; 1.2909x over previous
#include <cuda_runtime.h>
#include <cuda_bf16.h>
#include <math.h>
#include <stdint.h>

// Problem constants
#define NM 1024
#define NH 16
#define ND 64
#define BATCH 4
#define SEQ 1024
#define ROWS (BATCH*SEQ)   // 4096

// ---------------------------------------------------------------------------
// Scratch (device globals; no allocation allowed)
// ---------------------------------------------------------------------------
__device__ __nv_bfloat16 g_xh[ROWS * NM], g_xl[ROWS * NM];
__device__ __nv_bfloat16 g_wh[4][NM * NM], g_wl[4][NM * NM];
__device__ __nv_bfloat16 g_qh[ROWS * NM], g_ql[ROWS * NM];
__device__ __nv_bfloat16 g_kh[ROWS * NM], g_kl[ROWS * NM];
__device__ __nv_bfloat16 g_vh[ROWS * NM], g_vl[ROWS * NM];
__device__ __nv_bfloat16 g_ch[ROWS * NM], g_cl[ROWS * NM];
__device__ __nv_bfloat16 g_mb[BATCH * SEQ * SEQ];

// ===========================================================================
// Helpers
// ===========================================================================
__device__ __forceinline__ uint32_t smem_u32(const void* p) {
    uint32_t a;
    asm("{ .reg .u64 t; cvta.to.shared.u64 t, %1; cvt.u32.u64 %0, t; }"
        : "=r"(a) : "l"(p));
    return a;
}
__device__ __forceinline__ void cp16(uint32_t dst, const void* src) {
    asm volatile("cp.async.cg.shared.global [%0], [%1], 16;"
                 :: "r"(dst), "l"(src));
}
__device__ __forceinline__ void cp_commit() {
    asm volatile("cp.async.commit_group;");
}
template<int N> __device__ __forceinline__ void cp_wait() {
    asm volatile("cp.async.wait_group %0;" :: "n"(N));
}
__device__ __forceinline__ void ldm_x4(uint32_t* r, uint32_t a) {
    asm volatile("ldmatrix.sync.aligned.m8n8.x4.shared.b16 {%0,%1,%2,%3}, [%4];"
                 : "=r"(r[0]), "=r"(r[1]), "=r"(r[2]), "=r"(r[3]) : "r"(a));
}
__device__ __forceinline__ void ldm_x4t(uint32_t* r, uint32_t a) {
    asm volatile("ldmatrix.sync.aligned.m8n8.x4.trans.shared.b16 {%0,%1,%2,%3}, [%4];"
                 : "=r"(r[0]), "=r"(r[1]), "=r"(r[2]), "=r"(r[3]) : "r"(a));
}
__device__ __forceinline__ void ldm_x2(uint32_t* r, uint32_t a) {
    asm volatile("ldmatrix.sync.aligned.m8n8.x2.shared.b16 {%0,%1}, [%2];"
                 : "=r"(r[0]), "=r"(r[1]) : "r"(a));
}
__device__ __forceinline__ void mma_bf16(float* c, const uint32_t* a,
                                         const uint32_t* b) {
    asm volatile(
        "mma.sync.aligned.m16n8k16.row.col.f32.bf16.bf16.f32 "
        "{%0,%1,%2,%3}, {%4,%5,%6,%7}, {%8,%9}, {%0,%1,%2,%3};"
        : "+f"(c[0]), "+f"(c[1]), "+f"(c[2]), "+f"(c[3])
        : "r"(a[0]), "r"(a[1]), "r"(a[2]), "r"(a[3]), "r"(b[0]), "r"(b[1]));
}
__device__ __forceinline__ void split2(float x, float y, uint32_t& hi, uint32_t& lo) {
    __nv_bfloat162 h = __floats2bfloat162_rn(x, y);
    float2 hf = __bfloat1622float2(h);
    __nv_bfloat162 l = __floats2bfloat162_rn(x - hf.x, y - hf.y);
    hi = reinterpret_cast<uint32_t&>(h);
    lo = reinterpret_cast<uint32_t&>(l);
}

// ===========================================================================
// Conversion kernels (one-time)
// ===========================================================================
__global__ void conv_split(const float* __restrict__ in,
                           __nv_bfloat16* __restrict__ oh,
                           __nv_bfloat16* __restrict__ ol)
{
    int i = (blockIdx.x * 256 + threadIdx.x) * 4;
    float4 a = *(const float4*)(in + i);
    uint2 h, l;
    split2(a.x, a.y, h.x, l.x);
    split2(a.z, a.w, h.y, l.y);
    *(uint2*)(oh + i) = h;
    *(uint2*)(ol + i) = l;
}

__global__ void conv_mask(const int* __restrict__ m,
                          __nv_bfloat16* __restrict__ mb)
{
    int i = (blockIdx.x * 256 + threadIdx.x) * 4;
    int4 a = *(const int4*)(m + i);
    float f0 = (float)(a.x - 1) * 1e9f;
    float f1 = (float)(a.y - 1) * 1e9f;
    float f2 = (float)(a.z - 1) * 1e9f;
    float f3 = (float)(a.w - 1) * 1e9f;
    __nv_bfloat162 p0 = __floats2bfloat162_rn(f0, f1);
    __nv_bfloat162 p1 = __floats2bfloat162_rn(f2, f3);
    uint2 o;
    o.x = reinterpret_cast<uint32_t&>(p0);
    o.y = reinterpret_cast<uint32_t&>(p1);
    *(uint2*)(mb + i) = o;
}

// ===========================================================================
// bf16-split GEMM v2: pre-split inputs, cp.async double buffer.
// C = A W^T + bias ; A = Ah+Al [4096x1024], W = Wh+Wl [1024x1024].
// mode 0: write Ch/Cl split bf16 ; mode 1: write fp32 Cf.
// ===========================================================================
#define BKP 40
#define ASZB (128 * BKP * 2)      // 10240 bytes per array
#define SSTG (4 * ASZB)           // 40960 bytes per stage
#define GSMEM (2 * SSTG)          // 81920

__global__ __launch_bounds__(256)
void gemm_mma2(const __nv_bfloat16* __restrict__ Ah_g,
               const __nv_bfloat16* __restrict__ Al_g,
               const __nv_bfloat16* __restrict__ Bh_g,
               const __nv_bfloat16* __restrict__ Bl_g,
               const float* __restrict__ bias,
               float* __restrict__ Cf,
               __nv_bfloat16* __restrict__ Ch,
               __nv_bfloat16* __restrict__ Cl,
               int mode)
{
    extern __shared__ __align__(16) char smg[];
    const uint32_t sb = smem_u32(smg);

    const int tid  = threadIdx.x;
    const int lane = tid & 31;
    const int wid  = tid >> 5;
    const int wm   = (wid >> 2) * 64;
    const int wn   = (wid & 3) * 32;
    const int m0   = blockIdx.y * 128;
    const int n0   = blockIdx.x * 128;

    const __nv_bfloat16* gsrc[4] = {
        Ah_g + (size_t)m0 * 1024, Al_g + (size_t)m0 * 1024,
        Bh_g + (size_t)n0 * 1024, Bl_g + (size_t)n0 * 1024 };

    const uint32_t a_off = ((wm + (lane & 15)) * BKP + (lane >> 4) * 8) * 2;
    const uint32_t b_off = ((wn + (lane & 7)) * BKP + ((lane >> 3) & 1) * 8) * 2;

    float acc[4][4][4];
#pragma unroll
    for (int i = 0; i < 4; i++)
#pragma unroll
        for (int j = 0; j < 4; j++)
#pragma unroll
            for (int r = 0; r < 4; r++) acc[i][j][r] = 0.0f;

    // ---- load stage macro: 8 chunks/thread (2 per array) ----
#define GLOAD(stg, kc) do {                                                  \
    uint32_t _sbase = sb + (stg) * SSTG;                                     \
    _Pragma("unroll")                                                        \
    for (int j = 0; j < 8; j++) {                                            \
        int arr = j >> 1;                                                    \
        int w   = tid + (j & 1) * 256;                                       \
        int row = w >> 2;                                                    \
        int c8  = (w & 3) * 8;                                               \
        cp16(_sbase + arr * ASZB + (uint32_t)(row * BKP + c8) * 2,           \
             gsrc[arr] + (size_t)row * 1024 + (kc) + c8);                    \
    } } while (0)

    GLOAD(0, 0);
    cp_commit();

    for (int kc = 0; kc < 32; kc++) {
        int s = kc & 1;
        if (kc < 31) {
            GLOAD(s ^ 1, (kc + 1) * 32);
            cp_commit();
            cp_wait<1>();
        } else {
            cp_wait<0>();
        }
        __syncthreads();

        const uint32_t sAh = sb + s * SSTG;
        const uint32_t sAl = sAh + ASZB;
        const uint32_t sBh = sAh + 2 * ASZB;
        const uint32_t sBl = sAh + 3 * ASZB;

#pragma unroll
        for (int ks = 0; ks < 2; ks++) {
            const uint32_t kb = ks * 16 * 2;

            uint32_t ahf[4][4], alf[4][4];
#pragma unroll
            for (int tm = 0; tm < 4; tm++) {
                uint32_t o = a_off + kb + tm * (16 * BKP * 2);
                ldm_x4(ahf[tm], sAh + o);
                ldm_x4(alf[tm], sAl + o);
            }

            uint32_t bf[4][2];
#pragma unroll
            for (int tn = 0; tn < 4; tn++)
                ldm_x2(bf[tn], sBh + b_off + kb + tn * (8 * BKP * 2));
#pragma unroll
            for (int tm = 0; tm < 4; tm++)
#pragma unroll
                for (int tn = 0; tn < 4; tn++)
                    mma_bf16(acc[tm][tn], ahf[tm], bf[tn]);
#pragma unroll
            for (int tm = 0; tm < 4; tm++)
#pragma unroll
                for (int tn = 0; tn < 4; tn++)
                    mma_bf16(acc[tm][tn], alf[tm], bf[tn]);

#pragma unroll
            for (int tn = 0; tn < 4; tn++)
                ldm_x2(bf[tn], sBl + b_off + kb + tn * (8 * BKP * 2));
#pragma unroll
            for (int tm = 0; tm < 4; tm++)
#pragma unroll
                for (int tn = 0; tn < 4; tn++)
                    mma_bf16(acc[tm][tn], ahf[tm], bf[tn]);
        }
        __syncthreads();
    }
#undef GLOAD

    // ---- epilogue ----
    const int qr = lane >> 2;
    const int qc = (lane & 3) * 2;
    if (mode == 0) {
#pragma unroll
        for (int tm = 0; tm < 4; tm++) {
            int row = m0 + wm + tm * 16 + qr;
#pragma unroll
            for (int tn = 0; tn < 4; tn++) {
                int col = n0 + wn + tn * 8 + qc;
                float b0 = bias[col], b1 = bias[col + 1];
                uint32_t h, l;
                split2(acc[tm][tn][0] + b0, acc[tm][tn][1] + b1, h, l);
                *(uint32_t*)(Ch + (size_t)row * 1024 + col) = h;
                *(uint32_t*)(Cl + (size_t)row * 1024 + col) = l;
                split2(acc[tm][tn][2] + b0, acc[tm][tn][3] + b1, h, l);
                *(uint32_t*)(Ch + (size_t)(row + 8) * 1024 + col) = h;
                *(uint32_t*)(Cl + (size_t)(row + 8) * 1024 + col) = l;
            }
        }
    } else {
#pragma unroll
        for (int tm = 0; tm < 4; tm++) {
            int row = m0 + wm + tm * 16 + qr;
#pragma unroll
            for (int tn = 0; tn < 4; tn++) {
                int col = n0 + wn + tn * 8 + qc;
                float b0 = bias[col], b1 = bias[col + 1];
                *(float2*)(Cf + (size_t)row * 1024 + col) =
                    make_float2(acc[tm][tn][0] + b0, acc[tm][tn][1] + b1);
                *(float2*)(Cf + (size_t)(row + 8) * 1024 + col) =
                    make_float2(acc[tm][tn][2] + b0, acc[tm][tn][3] + b1);
            }
        }
    }
}

// ===========================================================================
// Tensor-core flash attention v2 — pre-split bf16 inputs, cp.async staging.
// CTA: 128 q-rows x one head. 8 warps x 16 rows.
// ===========================================================================
#define ALD 72
#define ABUF (128 * ALD * 2)   // 18432 bytes per buffer

__global__ __launch_bounds__(256)
void attn_mma2(const __nv_bfloat16* __restrict__ qh, const __nv_bfloat16* __restrict__ ql,
               const __nv_bfloat16* __restrict__ kh, const __nv_bfloat16* __restrict__ kl,
               const __nv_bfloat16* __restrict__ vh, const __nv_bfloat16* __restrict__ vl,
               const __nv_bfloat16* __restrict__ mb,
               __nv_bfloat16* __restrict__ ch, __nv_bfloat16* __restrict__ cl)
{
    extern __shared__ __align__(16) char sma[];
    const uint32_t sQh = smem_u32(sma);
    const uint32_t sQl = sQh + ABUF;
    const uint32_t sKh = sQh + 2 * ABUF;
    const uint32_t sKl = sQh + 3 * ABUF;
    const uint32_t sVh = sQh + 4 * ABUF;
    const uint32_t sVl = sQh + 5 * ABUF;

    const int tid  = threadIdx.x;
    const int lane = tid & 31;
    const int wid  = tid >> 5;
    const int q0   = blockIdx.x * 128;
    const int h    = blockIdx.y;
    const int b    = blockIdx.z;

    const size_t base  = (size_t)b * SEQ * NM + (size_t)h * ND;
    const size_t mbase = (size_t)b * SEQ * SEQ;

    // ---- Q tile load (cp.async) ----
#pragma unroll
    for (int j = 0; j < 8; j++) {
        int arr = j >> 2;
        int w   = tid + (j & 3) * 256;
        int row = w >> 3;
        int c8  = (w & 7) * 8;
        const __nv_bfloat16* src =
            (arr ? ql : qh) + base + (size_t)(q0 + row) * 1024 + c8;
        cp16((arr ? sQl : sQh) + (uint32_t)(row * ALD + c8) * 2, src);
    }
    cp_commit();
    cp_wait<0>();
    __syncthreads();

    // ---- persistent Q fragments ----
    uint32_t qfh[4][4], qfl[4][4];
    {
        uint32_t qo = ((wid * 16 + (lane & 15)) * ALD + (lane >> 4) * 8) * 2;
#pragma unroll
        for (int ks = 0; ks < 4; ks++) {
            ldm_x4(qfh[ks], sQh + qo + ks * 32);
            ldm_x4(qfl[ks], sQl + qo + ks * 32);
        }
    }

    float oacc[8][4];
#pragma unroll
    for (int i = 0; i < 8; i++)
#pragma unroll
        for (int r = 0; r < 4; r++) oacc[i][r] = 0.0f;
    float mr1 = -INFINITY, mr2 = -INFINITY, lr1 = 0.0f, lr2 = 0.0f;

    const float SCALE = 0.03125f;
    const int r1 = wid * 16 + (lane >> 2);

    const uint32_t koff = ((lane & 7) * ALD + ((lane >> 3) & 3) * 8) * 2;
    const uint32_t voff = (((lane & 7) + 8 * ((lane >> 3) & 1)) * ALD) * 2
                        + ((lane >> 4) & 1) * 16;

    const __nv_bfloat16* ksrc[4] = { kh + base, kl + base, vh + base, vl + base };
    const uint32_t kdst[4] = { sKh, sKl, sVh, sVl };

    for (int t = 0; t < 8; t++) {
        const int k0 = t * 128;
        // ---- K/V tiles (cp.async) ----
#pragma unroll
        for (int j = 0; j < 16; j++) {
            int arr = j >> 2;
            int w   = tid + (j & 3) * 256;
            int row = w >> 3;
            int c8  = (w & 7) * 8;
            cp16(kdst[arr] + (uint32_t)(row * ALD + c8) * 2,
                 ksrc[arr] + (size_t)(k0 + row) * 1024 + c8);
        }
        cp_commit();
        cp_wait<0>();
        __syncthreads();

        // ---- S = Q K^T ----
        float sacc[16][4];
#pragma unroll
        for (int j = 0; j < 16; j++) {
#pragma unroll
            for (int r = 0; r < 4; r++) sacc[j][r] = 0.0f;
            uint32_t ka = koff + (uint32_t)(j * 8 * ALD * 2);
            uint32_t khf[8], klf[8];
            ldm_x4(khf,     sKh + ka);
            ldm_x4(khf + 4, sKh + ka + 64);
            ldm_x4(klf,     sKl + ka);
            ldm_x4(klf + 4, sKl + ka + 64);
#pragma unroll
            for (int ks = 0; ks < 4; ks++) {
                mma_bf16(sacc[j], qfh[ks], &khf[ks * 2]);
                mma_bf16(sacc[j], qfl[ks], &khf[ks * 2]);
                mma_bf16(sacc[j], qfh[ks], &klf[ks * 2]);
            }
        }

        // ---- mask (additive bf16) + scale + row max ----
        const __nv_bfloat16* mp =
            mb + mbase + (size_t)(q0 + r1) * SEQ + k0 + (lane & 3) * 2;
        float rmax1 = -INFINITY, rmax2 = -INFINITY;
#pragma unroll
        for (int j = 0; j < 16; j++) {
            uint32_t ma = *(const uint32_t*)(mp + j * 8);
            uint32_t mc = *(const uint32_t*)(mp + 8 * SEQ + j * 8);
            float2 f1 = __bfloat1622float2(reinterpret_cast<__nv_bfloat162&>(ma));
            float2 f2 = __bfloat1622float2(reinterpret_cast<__nv_bfloat162&>(mc));
            sacc[j][0] = sacc[j][0] * SCALE + f1.x;
            sacc[j][1] = sacc[j][1] * SCALE + f1.y;
            sacc[j][2] = sacc[j][2] * SCALE + f2.x;
            sacc[j][3] = sacc[j][3] * SCALE + f2.y;
            rmax1 = fmaxf(rmax1, fmaxf(sacc[j][0], sacc[j][1]));
            rmax2 = fmaxf(rmax2, fmaxf(sacc[j][2], sacc[j][3]));
        }
#pragma unroll
        for (int off = 1; off < 4; off <<= 1) {
            rmax1 = fmaxf(rmax1, __shfl_xor_sync(0xffffffffu, rmax1, off));
            rmax2 = fmaxf(rmax2, __shfl_xor_sync(0xffffffffu, rmax2, off));
        }

        // ---- online softmax ----
        float mn1 = fmaxf(mr1, rmax1);
        float mn2 = fmaxf(mr2, rmax2);
        float c1 = __expf(mr1 - mn1);
        float c2 = __expf(mr2 - mn2);
        mr1 = mn1; mr2 = mn2;
#pragma unroll
        for (int i = 0; i < 8; i++) {
            oacc[i][0] *= c1; oacc[i][1] *= c1;
            oacc[i][2] *= c2; oacc[i][3] *= c2;
        }
        float rs1 = 0.0f, rs2 = 0.0f;
#pragma unroll
        for (int j = 0; j < 16; j++) {
            sacc[j][0] = __expf(sacc[j][0] - mn1);
            sacc[j][1] = __expf(sacc[j][1] - mn1);
            sacc[j][2] = __expf(sacc[j][2] - mn2);
            sacc[j][3] = __expf(sacc[j][3] - mn2);
            rs1 += sacc[j][0] + sacc[j][1];
            rs2 += sacc[j][2] + sacc[j][3];
        }
#pragma unroll
        for (int off = 1; off < 4; off <<= 1) {
            rs1 += __shfl_xor_sync(0xffffffffu, rs1, off);
            rs2 += __shfl_xor_sync(0xffffffffu, rs2, off);
        }
        lr1 = lr1 * c1 + rs1;
        lr2 = lr2 * c2 + rs2;

        // ---- O += P V ----
#pragma unroll
        for (int ks = 0; ks < 8; ks++) {
            uint32_t ph[4], pl[4];
            split2(sacc[2*ks][0],   sacc[2*ks][1],   ph[0], pl[0]);
            split2(sacc[2*ks][2],   sacc[2*ks][3],   ph[1], pl[1]);
            split2(sacc[2*ks+1][0], sacc[2*ks+1][1], ph[2], pl[2]);
            split2(sacc[2*ks+1][2], sacc[2*ks+1][3], ph[3], pl[3]);

            uint32_t va = voff + (uint32_t)(ks * 16 * ALD * 2);
#pragma unroll
            for (int tp = 0; tp < 4; tp++) {
                uint32_t vhf[4], vlf[4];
                ldm_x4t(vhf, sVh + va + tp * 32);
                ldm_x4t(vlf, sVl + va + tp * 32);
                mma_bf16(oacc[2*tp],   ph, &vhf[0]);
                mma_bf16(oacc[2*tp+1], ph, &vhf[2]);
                mma_bf16(oacc[2*tp],   pl, &vhf[0]);
                mma_bf16(oacc[2*tp+1], pl, &vhf[2]);
                mma_bf16(oacc[2*tp],   ph, &vlf[0]);
                mma_bf16(oacc[2*tp+1], ph, &vlf[2]);
            }
        }
        __syncthreads();
    }

    // ---- normalize + store ctx (split bf16) ----
    float i1 = 1.0f / lr1, i2 = 1.0f / lr2;
    size_t off0 = base + (size_t)(q0 + r1) * NM + (lane & 3) * 2;
#pragma unroll
    for (int tn = 0; tn < 8; tn++) {
        uint32_t hh, ll;
        split2(oacc[tn][0] * i1, oacc[tn][1] * i1, hh, ll);
        *(uint32_t*)(ch + off0 + tn * 8) = hh;
        *(uint32_t*)(cl + off0 + tn * 8) = ll;
        split2(oacc[tn][2] * i2, oacc[tn][3] * i2, hh, ll);
        *(uint32_t*)(ch + off0 + 8 * NM + tn * 8) = hh;
        *(uint32_t*)(cl + off0 + 8 * NM + tn * 8) = ll;
    }
}

// ---------------------------------------------------------------------------
// kernel_launch — inputs: x, mask, Wq, bq, Wk, bk, Wv, bv, Wo, bo
// ---------------------------------------------------------------------------
extern "C" void kernel_launch(void* const* d_in, const int* in_sizes, int n_in,
                              void* d_out, int out_size)
{
    const float* x    = (const float*)d_in[0];
    const int*   mask = (const int*)  d_in[1];
    const float* Wq   = (const float*)d_in[2];
    const float* bq   = (const float*)d_in[3];
    const float* Wk   = (const float*)d_in[4];
    const float* bk   = (const float*)d_in[5];
    const float* Wv   = (const float*)d_in[6];
    const float* bv   = (const float*)d_in[7];
    const float* Wo   = (const float*)d_in[8];
    const float* bo   = (const float*)d_in[9];
    float* out = (float*)d_out;

    __nv_bfloat16 *xh, *xl, *wh, *wl, *qh, *ql, *kh, *kl, *vh, *vl, *ch, *cl, *mbp;
    cudaGetSymbolAddress((void**)&xh, g_xh);
    cudaGetSymbolAddress((void**)&xl, g_xl);
    cudaGetSymbolAddress((void**)&wh, g_wh);
    cudaGetSymbolAddress((void**)&wl, g_wl);
    cudaGetSymbolAddress((void**)&qh, g_qh);
    cudaGetSymbolAddress((void**)&ql, g_ql);
    cudaGetSymbolAddress((void**)&kh, g_kh);
    cudaGetSymbolAddress((void**)&kl, g_kl);
    cudaGetSymbolAddress((void**)&vh, g_vh);
    cudaGetSymbolAddress((void**)&vl, g_vl);
    cudaGetSymbolAddress((void**)&ch, g_ch);
    cudaGetSymbolAddress((void**)&cl, g_cl);
    cudaGetSymbolAddress((void**)&mbp, g_mb);

    // ---- conversions ----
    conv_split<<<ROWS * NM / 1024, 256>>>(x, xh, xl);
    conv_split<<<NM * NM / 1024, 256>>>(Wq, wh + 0 * NM * NM, wl + 0 * NM * NM);
    conv_split<<<NM * NM / 1024, 256>>>(Wk, wh + 1 * NM * NM, wl + 1 * NM * NM);
    conv_split<<<NM * NM / 1024, 256>>>(Wv, wh + 2 * NM * NM, wl + 2 * NM * NM);
    conv_split<<<NM * NM / 1024, 256>>>(Wo, wh + 3 * NM * NM, wl + 3 * NM * NM);
    conv_mask<<<BATCH * SEQ * SEQ / 1024, 256>>>(mask, mbp);

    // ---- QKV projections ----
    cudaFuncSetAttribute(gemm_mma2,
                         cudaFuncAttributeMaxDynamicSharedMemorySize, GSMEM);
    dim3 gblock(256);
    dim3 ggrid(NM / 128, ROWS / 128);
    gemm_mma2<<<ggrid, gblock, GSMEM>>>(xh, xl, wh + 0 * NM * NM, wl + 0 * NM * NM,
                                        bq, nullptr, qh, ql, 0);
    gemm_mma2<<<ggrid, gblock, GSMEM>>>(xh, xl, wh + 1 * NM * NM, wl + 1 * NM * NM,
                                        bk, nullptr, kh, kl, 0);
    gemm_mma2<<<ggrid, gblock, GSMEM>>>(xh, xl, wh + 2 * NM * NM, wl + 2 * NM * NM,
                                        bv, nullptr, vh, vl, 0);

    // ---- attention ----
    const int asmem = 6 * ABUF;   // 110592
    cudaFuncSetAttribute(attn_mma2,
                         cudaFuncAttributeMaxDynamicSharedMemorySize, asmem);
    dim3 agrid(SEQ / 128, NH, BATCH);
    attn_mma2<<<agrid, 256, asmem>>>(qh, ql, kh, kl, vh, vl, mbp, ch, cl);

    // ---- output projection ----
    gemm_mma2<<<ggrid, gblock, GSMEM>>>(ch, cl, wh + 3 * NM * NM, wl + 3 * NM * NM,
                                        bo, out, nullptr, nullptr, 1);
}

// round 7
// speedup vs baseline: 2.7849x; 1.0017x over previous
#include <cuda_runtime.h>
#include <cuda_bf16.h>
#include <math.h>
#include <stdint.h>

// Problem constants
#define NM 1024
#define NH 16
#define ND 64
#define BATCH 4
#define SEQ 1024
#define ROWS (BATCH*SEQ)   // 4096

// ---------------------------------------------------------------------------
// Scratch (device globals; no allocation allowed)
// ---------------------------------------------------------------------------
__device__ __nv_bfloat16 g_xh[ROWS * NM], g_xl[ROWS * NM];
__device__ __nv_bfloat16 g_wh[4][NM * NM], g_wl[4][NM * NM];
__device__ __nv_bfloat16 g_qh[ROWS * NM], g_ql[ROWS * NM];
__device__ __nv_bfloat16 g_kh[ROWS * NM], g_kl[ROWS * NM];
__device__ __nv_bfloat16 g_vh[ROWS * NM], g_vl[ROWS * NM];
__device__ __nv_bfloat16 g_ch[ROWS * NM], g_cl[ROWS * NM];
__device__ __nv_bfloat16 g_mb[BATCH * SEQ * SEQ];

// ===========================================================================
// Helpers
// ===========================================================================
__device__ __forceinline__ uint32_t smem_u32(const void* p) {
    uint32_t a;
    asm("{ .reg .u64 t; cvta.to.shared.u64 t, %1; cvt.u32.u64 %0, t; }"
        : "=r"(a) : "l"(p));
    return a;
}
__device__ __forceinline__ void cp16(uint32_t dst, const void* src) {
    asm volatile("cp.async.cg.shared.global [%0], [%1], 16;"
                 :: "r"(dst), "l"(src));
}
__device__ __forceinline__ void cp_commit() {
    asm volatile("cp.async.commit_group;");
}
template<int N> __device__ __forceinline__ void cp_wait() {
    asm volatile("cp.async.wait_group %0;" :: "n"(N));
}
__device__ __forceinline__ void ldm_x4(uint32_t* r, uint32_t a) {
    asm volatile("ldmatrix.sync.aligned.m8n8.x4.shared.b16 {%0,%1,%2,%3}, [%4];"
                 : "=r"(r[0]), "=r"(r[1]), "=r"(r[2]), "=r"(r[3]) : "r"(a));
}
__device__ __forceinline__ void ldm_x4t(uint32_t* r, uint32_t a) {
    asm volatile("ldmatrix.sync.aligned.m8n8.x4.trans.shared.b16 {%0,%1,%2,%3}, [%4];"
                 : "=r"(r[0]), "=r"(r[1]), "=r"(r[2]), "=r"(r[3]) : "r"(a));
}
__device__ __forceinline__ void ldm_x2(uint32_t* r, uint32_t a) {
    asm volatile("ldmatrix.sync.aligned.m8n8.x2.shared.b16 {%0,%1}, [%2];"
                 : "=r"(r[0]), "=r"(r[1]) : "r"(a));
}
__device__ __forceinline__ void mma_bf16(float* c, const uint32_t* a,
                                         const uint32_t* b) {
    asm volatile(
        "mma.sync.aligned.m16n8k16.row.col.f32.bf16.bf16.f32 "
        "{%0,%1,%2,%3}, {%4,%5,%6,%7}, {%8,%9}, {%0,%1,%2,%3};"
        : "+f"(c[0]), "+f"(c[1]), "+f"(c[2]), "+f"(c[3])
        : "r"(a[0]), "r"(a[1]), "r"(a[2]), "r"(a[3]), "r"(b[0]), "r"(b[1]));
}
__device__ __forceinline__ void split2(float x, float y, uint32_t& hi, uint32_t& lo) {
    __nv_bfloat162 h = __floats2bfloat162_rn(x, y);
    float2 hf = __bfloat1622float2(h);
    __nv_bfloat162 l = __floats2bfloat162_rn(x - hf.x, y - hf.y);
    hi = reinterpret_cast<uint32_t&>(h);
    lo = reinterpret_cast<uint32_t&>(l);
}

// ===========================================================================
// Conversion kernels (one-time)
// ===========================================================================
__global__ void conv_split(const float* __restrict__ in,
                           __nv_bfloat16* __restrict__ oh,
                           __nv_bfloat16* __restrict__ ol)
{
    int i = (blockIdx.x * 256 + threadIdx.x) * 4;
    float4 a = *(const float4*)(in + i);
    uint2 h, l;
    split2(a.x, a.y, h.x, l.x);
    split2(a.z, a.w, h.y, l.y);
    *(uint2*)(oh + i) = h;
    *(uint2*)(ol + i) = l;
}

__global__ void conv_mask(const int* __restrict__ m,
                          __nv_bfloat16* __restrict__ mb)
{
    int i = (blockIdx.x * 256 + threadIdx.x) * 4;
    int4 a = *(const int4*)(m + i);
    float f0 = (float)(a.x - 1) * 1e9f;
    float f1 = (float)(a.y - 1) * 1e9f;
    float f2 = (float)(a.z - 1) * 1e9f;
    float f3 = (float)(a.w - 1) * 1e9f;
    __nv_bfloat162 p0 = __floats2bfloat162_rn(f0, f1);
    __nv_bfloat162 p1 = __floats2bfloat162_rn(f2, f3);
    uint2 o;
    o.x = reinterpret_cast<uint32_t&>(p0);
    o.y = reinterpret_cast<uint32_t&>(p1);
    *(uint2*)(mb + i) = o;
}

// ===========================================================================
// bf16-split GEMM v3: occ-2 (128 regs), register-lean inner loop.
// C = A W^T + bias ; pre-split bf16 inputs, cp.async double buffer.
// mode 0: write Ch/Cl split bf16 ; mode 1: write fp32 Cf.
// ===========================================================================
#define BKP 40
#define ASZB (128 * BKP * 2)      // 10240 bytes per array
#define SSTG (4 * ASZB)           // 40960 bytes per stage
#define GSMEM (2 * SSTG)          // 81920

__global__ __launch_bounds__(256, 2)
void gemm_mma2(const __nv_bfloat16* __restrict__ Ah_g,
               const __nv_bfloat16* __restrict__ Al_g,
               const __nv_bfloat16* __restrict__ Bh_g,
               const __nv_bfloat16* __restrict__ Bl_g,
               const float* __restrict__ bias,
               float* __restrict__ Cf,
               __nv_bfloat16* __restrict__ Ch,
               __nv_bfloat16* __restrict__ Cl,
               int mode)
{
    extern __shared__ __align__(16) char smg[];
    const uint32_t sb = smem_u32(smg);

    const int tid  = threadIdx.x;
    const int lane = tid & 31;
    const int wid  = tid >> 5;
    const int wm   = (wid >> 2) * 64;
    const int wn   = (wid & 3) * 32;
    const int m0   = blockIdx.y * 128;
    const int n0   = blockIdx.x * 128;

    const __nv_bfloat16* gsrc[4] = {
        Ah_g + (size_t)m0 * 1024, Al_g + (size_t)m0 * 1024,
        Bh_g + (size_t)n0 * 1024, Bl_g + (size_t)n0 * 1024 };

    const uint32_t a_off = ((wm + (lane & 15)) * BKP + (lane >> 4) * 8) * 2;
    const uint32_t b_off = ((wn + (lane & 7)) * BKP + ((lane >> 3) & 1) * 8) * 2;

    float acc[4][4][4];
#pragma unroll
    for (int i = 0; i < 4; i++)
#pragma unroll
        for (int j = 0; j < 4; j++)
#pragma unroll
            for (int r = 0; r < 4; r++) acc[i][j][r] = 0.0f;

#define GLOAD(stg, kc) do {                                                  \
    uint32_t _sbase = sb + (stg) * SSTG;                                     \
    _Pragma("unroll")                                                        \
    for (int j = 0; j < 8; j++) {                                            \
        int arr = j >> 1;                                                    \
        int w   = tid + (j & 1) * 256;                                       \
        int row = w >> 2;                                                    \
        int c8  = (w & 3) * 8;                                               \
        cp16(_sbase + arr * ASZB + (uint32_t)(row * BKP + c8) * 2,           \
             gsrc[arr] + (size_t)row * 1024 + (kc) + c8);                    \
    } } while (0)

    GLOAD(0, 0);
    cp_commit();

    for (int kc = 0; kc < 32; kc++) {
        int s = kc & 1;
        if (kc < 31) {
            GLOAD(s ^ 1, (kc + 1) * 32);
            cp_commit();
            cp_wait<1>();
        } else {
            cp_wait<0>();
        }
        __syncthreads();

        const uint32_t sAh = sb + s * SSTG;
        const uint32_t sAl = sAh + ASZB;
        const uint32_t sBh = sAh + 2 * ASZB;
        const uint32_t sBl = sAh + 3 * ASZB;

#pragma unroll
        for (int ks = 0; ks < 2; ks++) {
            const uint32_t kb = ks * 16 * 2;

            uint32_t af[4][4];          // A fragments (hi first, then lo)
            uint32_t bfh[4][2], bfl[4][2];

            // --- load A-hi + B-hi ---
#pragma unroll
            for (int tm = 0; tm < 4; tm++)
                ldm_x4(af[tm], sAh + a_off + kb + tm * (16 * BKP * 2));
#pragma unroll
            for (int tn = 0; tn < 4; tn++)
                ldm_x2(bfh[tn], sBh + b_off + kb + tn * (8 * BKP * 2));

            // --- hi*hi ---
#pragma unroll
            for (int tm = 0; tm < 4; tm++)
#pragma unroll
                for (int tn = 0; tn < 4; tn++)
                    mma_bf16(acc[tm][tn], af[tm], bfh[tn]);

            // --- load B-lo, hi*lo ---
#pragma unroll
            for (int tn = 0; tn < 4; tn++)
                ldm_x2(bfl[tn], sBl + b_off + kb + tn * (8 * BKP * 2));
#pragma unroll
            for (int tm = 0; tm < 4; tm++)
#pragma unroll
                for (int tn = 0; tn < 4; tn++)
                    mma_bf16(acc[tm][tn], af[tm], bfl[tn]);

            // --- overwrite A regs with A-lo, lo*hi ---
#pragma unroll
            for (int tm = 0; tm < 4; tm++)
                ldm_x4(af[tm], sAl + a_off + kb + tm * (16 * BKP * 2));
#pragma unroll
            for (int tm = 0; tm < 4; tm++)
#pragma unroll
                for (int tn = 0; tn < 4; tn++)
                    mma_bf16(acc[tm][tn], af[tm], bfh[tn]);
        }
        __syncthreads();
    }
#undef GLOAD

    // ---- epilogue ----
    const int qr = lane >> 2;
    const int qc = (lane & 3) * 2;
    if (mode == 0) {
#pragma unroll
        for (int tm = 0; tm < 4; tm++) {
            int row = m0 + wm + tm * 16 + qr;
#pragma unroll
            for (int tn = 0; tn < 4; tn++) {
                int col = n0 + wn + tn * 8 + qc;
                float b0 = bias[col], b1 = bias[col + 1];
                uint32_t h, l;
                split2(acc[tm][tn][0] + b0, acc[tm][tn][1] + b1, h, l);
                *(uint32_t*)(Ch + (size_t)row * 1024 + col) = h;
                *(uint32_t*)(Cl + (size_t)row * 1024 + col) = l;
                split2(acc[tm][tn][2] + b0, acc[tm][tn][3] + b1, h, l);
                *(uint32_t*)(Ch + (size_t)(row + 8) * 1024 + col) = h;
                *(uint32_t*)(Cl + (size_t)(row + 8) * 1024 + col) = l;
            }
        }
    } else {
#pragma unroll
        for (int tm = 0; tm < 4; tm++) {
            int row = m0 + wm + tm * 16 + qr;
#pragma unroll
            for (int tn = 0; tn < 4; tn++) {
                int col = n0 + wn + tn * 8 + qc;
                float b0 = bias[col], b1 = bias[col + 1];
                *(float2*)(Cf + (size_t)row * 1024 + col) =
                    make_float2(acc[tm][tn][0] + b0, acc[tm][tn][1] + b1);
                *(float2*)(Cf + (size_t)(row + 8) * 1024 + col) =
                    make_float2(acc[tm][tn][2] + b0, acc[tm][tn][3] + b1);
            }
        }
    }
}

// ===========================================================================
// Tensor-core flash attention v2 — pre-split bf16 inputs, cp.async staging.
// (unchanged from R5)
// ===========================================================================
#define ALD 72
#define ABUF (128 * ALD * 2)   // 18432 bytes per buffer

__global__ __launch_bounds__(256)
void attn_mma2(const __nv_bfloat16* __restrict__ qh, const __nv_bfloat16* __restrict__ ql,
               const __nv_bfloat16* __restrict__ kh, const __nv_bfloat16* __restrict__ kl,
               const __nv_bfloat16* __restrict__ vh, const __nv_bfloat16* __restrict__ vl,
               const __nv_bfloat16* __restrict__ mb,
               __nv_bfloat16* __restrict__ ch, __nv_bfloat16* __restrict__ cl)
{
    extern __shared__ __align__(16) char sma[];
    const uint32_t sQh = smem_u32(sma);
    const uint32_t sQl = sQh + ABUF;
    const uint32_t sKh = sQh + 2 * ABUF;
    const uint32_t sKl = sQh + 3 * ABUF;
    const uint32_t sVh = sQh + 4 * ABUF;
    const uint32_t sVl = sQh + 5 * ABUF;

    const int tid  = threadIdx.x;
    const int lane = tid & 31;
    const int wid  = tid >> 5;
    const int q0   = blockIdx.x * 128;
    const int h    = blockIdx.y;
    const int b    = blockIdx.z;

    const size_t base  = (size_t)b * SEQ * NM + (size_t)h * ND;
    const size_t mbase = (size_t)b * SEQ * SEQ;

#pragma unroll
    for (int j = 0; j < 8; j++) {
        int arr = j >> 2;
        int w   = tid + (j & 3) * 256;
        int row = w >> 3;
        int c8  = (w & 7) * 8;
        const __nv_bfloat16* src =
            (arr ? ql : qh) + base + (size_t)(q0 + row) * 1024 + c8;
        cp16((arr ? sQl : sQh) + (uint32_t)(row * ALD + c8) * 2, src);
    }
    cp_commit();
    cp_wait<0>();
    __syncthreads();

    uint32_t qfh[4][4], qfl[4][4];
    {
        uint32_t qo = ((wid * 16 + (lane & 15)) * ALD + (lane >> 4) * 8) * 2;
#pragma unroll
        for (int ks = 0; ks < 4; ks++) {
            ldm_x4(qfh[ks], sQh + qo + ks * 32);
            ldm_x4(qfl[ks], sQl + qo + ks * 32);
        }
    }

    float oacc[8][4];
#pragma unroll
    for (int i = 0; i < 8; i++)
#pragma unroll
        for (int r = 0; r < 4; r++) oacc[i][r] = 0.0f;
    float mr1 = -INFINITY, mr2 = -INFINITY, lr1 = 0.0f, lr2 = 0.0f;

    const float SCALE = 0.03125f;
    const int r1 = wid * 16 + (lane >> 2);

    const uint32_t koff = ((lane & 7) * ALD + ((lane >> 3) & 3) * 8) * 2;
    const uint32_t voff = (((lane & 7) + 8 * ((lane >> 3) & 1)) * ALD) * 2
                        + ((lane >> 4) & 1) * 16;

    const __nv_bfloat16* ksrc[4] = { kh + base, kl + base, vh + base, vl + base };
    const uint32_t kdst[4] = { sKh, sKl, sVh, sVl };

    for (int t = 0; t < 8; t++) {
        const int k0 = t * 128;
#pragma unroll
        for (int j = 0; j < 16; j++) {
            int arr = j >> 2;
            int w   = tid + (j & 3) * 256;
            int row = w >> 3;
            int c8  = (w & 7) * 8;
            cp16(kdst[arr] + (uint32_t)(row * ALD + c8) * 2,
                 ksrc[arr] + (size_t)(k0 + row) * 1024 + c8);
        }
        cp_commit();
        cp_wait<0>();
        __syncthreads();

        float sacc[16][4];
#pragma unroll
        for (int j = 0; j < 16; j++) {
#pragma unroll
            for (int r = 0; r < 4; r++) sacc[j][r] = 0.0f;
            uint32_t ka = koff + (uint32_t)(j * 8 * ALD * 2);
            uint32_t khf[8], klf[8];
            ldm_x4(khf,     sKh + ka);
            ldm_x4(khf + 4, sKh + ka + 64);
            ldm_x4(klf,     sKl + ka);
            ldm_x4(klf + 4, sKl + ka + 64);
#pragma unroll
            for (int ks = 0; ks < 4; ks++) {
                mma_bf16(sacc[j], qfh[ks], &khf[ks * 2]);
                mma_bf16(sacc[j], qfl[ks], &khf[ks * 2]);
                mma_bf16(sacc[j], qfh[ks], &klf[ks * 2]);
            }
        }

        const __nv_bfloat16* mp =
            mb + mbase + (size_t)(q0 + r1) * SEQ + k0 + (lane & 3) * 2;
        float rmax1 = -INFINITY, rmax2 = -INFINITY;
#pragma unroll
        for (int j = 0; j < 16; j++) {
            uint32_t ma = *(const uint32_t*)(mp + j * 8);
            uint32_t mc = *(const uint32_t*)(mp + 8 * SEQ + j * 8);
            float2 f1 = __bfloat1622float2(reinterpret_cast<__nv_bfloat162&>(ma));
            float2 f2 = __bfloat1622float2(reinterpret_cast<__nv_bfloat162&>(mc));
            sacc[j][0] = sacc[j][0] * SCALE + f1.x;
            sacc[j][1] = sacc[j][1] * SCALE + f1.y;
            sacc[j][2] = sacc[j][2] * SCALE + f2.x;
            sacc[j][3] = sacc[j][3] * SCALE + f2.y;
            rmax1 = fmaxf(rmax1, fmaxf(sacc[j][0], sacc[j][1]));
            rmax2 = fmaxf(rmax2, fmaxf(sacc[j][2], sacc[j][3]));
        }
#pragma unroll
        for (int off = 1; off < 4; off <<= 1) {
            rmax1 = fmaxf(rmax1, __shfl_xor_sync(0xffffffffu, rmax1, off));
            rmax2 = fmaxf(rmax2, __shfl_xor_sync(0xffffffffu, rmax2, off));
        }

        float mn1 = fmaxf(mr1, rmax1);
        float mn2 = fmaxf(mr2, rmax2);
        float c1 = __expf(mr1 - mn1);
        float c2 = __expf(mr2 - mn2);
        mr1 = mn1; mr2 = mn2;
#pragma unroll
        for (int i = 0; i < 8; i++) {
            oacc[i][0] *= c1; oacc[i][1] *= c1;
            oacc[i][2] *= c2; oacc[i][3] *= c2;
        }
        float rs1 = 0.0f, rs2 = 0.0f;
#pragma unroll
        for (int j = 0; j < 16; j++) {
            sacc[j][0] = __expf(sacc[j][0] - mn1);
            sacc[j][1] = __expf(sacc[j][1] - mn1);
            sacc[j][2] = __expf(sacc[j][2] - mn2);
            sacc[j][3] = __expf(sacc[j][3] - mn2);
            rs1 += sacc[j][0] + sacc[j][1];
            rs2 += sacc[j][2] + sacc[j][3];
        }
#pragma unroll
        for (int off = 1; off < 4; off <<= 1) {
            rs1 += __shfl_xor_sync(0xffffffffu, rs1, off);
            rs2 += __shfl_xor_sync(0xffffffffu, rs2, off);
        }
        lr1 = lr1 * c1 + rs1;
        lr2 = lr2 * c2 + rs2;

#pragma unroll
        for (int ks = 0; ks < 8; ks++) {
            uint32_t ph[4], pl[4];
            split2(sacc[2*ks][0],   sacc[2*ks][1],   ph[0], pl[0]);
            split2(sacc[2*ks][2],   sacc[2*ks][3],   ph[1], pl[1]);
            split2(sacc[2*ks+1][0], sacc[2*ks+1][1], ph[2], pl[2]);
            split2(sacc[2*ks+1][2], sacc[2*ks+1][3], ph[3], pl[3]);

            uint32_t va = voff + (uint32_t)(ks * 16 * ALD * 2);
#pragma unroll
            for (int tp = 0; tp < 4; tp++) {
                uint32_t vhf[4], vlf[4];
                ldm_x4t(vhf, sVh + va + tp * 32);
                ldm_x4t(vlf, sVl + va + tp * 32);
                mma_bf16(oacc[2*tp],   ph, &vhf[0]);
                mma_bf16(oacc[2*tp+1], ph, &vhf[2]);
                mma_bf16(oacc[2*tp],   pl, &vhf[0]);
                mma_bf16(oacc[2*tp+1], pl, &vhf[2]);
                mma_bf16(oacc[2*tp],   ph, &vlf[0]);
                mma_bf16(oacc[2*tp+1], ph, &vlf[2]);
            }
        }
        __syncthreads();
    }

    float i1 = 1.0f / lr1, i2 = 1.0f / lr2;
    size_t off0 = base + (size_t)(q0 + r1) * NM + (lane & 3) * 2;
#pragma unroll
    for (int tn = 0; tn < 8; tn++) {
        uint32_t hh, ll;
        split2(oacc[tn][0] * i1, oacc[tn][1] * i1, hh, ll);
        *(uint32_t*)(ch + off0 + tn * 8) = hh;
        *(uint32_t*)(cl + off0 + tn * 8) = ll;
        split2(oacc[tn][2] * i2, oacc[tn][3] * i2, hh, ll);
        *(uint32_t*)(ch + off0 + 8 * NM + tn * 8) = hh;
        *(uint32_t*)(cl + off0 + 8 * NM + tn * 8) = ll;
    }
}

// ---------------------------------------------------------------------------
// kernel_launch — inputs: x, mask, Wq, bq, Wk, bk, Wv, bv, Wo, bo
// ---------------------------------------------------------------------------
extern "C" void kernel_launch(void* const* d_in, const int* in_sizes, int n_in,
                              void* d_out, int out_size)
{
    const float* x    = (const float*)d_in[0];
    const int*   mask = (const int*)  d_in[1];
    const float* Wq   = (const float*)d_in[2];
    const float* bq   = (const float*)d_in[3];
    const float* Wk   = (const float*)d_in[4];
    const float* bk   = (const float*)d_in[5];
    const float* Wv   = (const float*)d_in[6];
    const float* bv   = (const float*)d_in[7];
    const float* Wo   = (const float*)d_in[8];
    const float* bo   = (const float*)d_in[9];
    float* out = (float*)d_out;

    __nv_bfloat16 *xh, *xl, *wh, *wl, *qh, *ql, *kh, *kl, *vh, *vl, *ch, *cl, *mbp;
    cudaGetSymbolAddress((void**)&xh, g_xh);
    cudaGetSymbolAddress((void**)&xl, g_xl);
    cudaGetSymbolAddress((void**)&wh, g_wh);
    cudaGetSymbolAddress((void**)&wl, g_wl);
    cudaGetSymbolAddress((void**)&qh, g_qh);
    cudaGetSymbolAddress((void**)&ql, g_ql);
    cudaGetSymbolAddress((void**)&kh, g_kh);
    cudaGetSymbolAddress((void**)&kl, g_kl);
    cudaGetSymbolAddress((void**)&vh, g_vh);
    cudaGetSymbolAddress((void**)&vl, g_vl);
    cudaGetSymbolAddress((void**)&ch, g_ch);
    cudaGetSymbolAddress((void**)&cl, g_cl);
    cudaGetSymbolAddress((void**)&mbp, g_mb);

    // ---- conversions ----
    conv_split<<<ROWS * NM / 1024, 256>>>(x, xh, xl);
    conv_split<<<NM * NM / 1024, 256>>>(Wq, wh + 0 * NM * NM, wl + 0 * NM * NM);
    conv_split<<<NM * NM / 1024, 256>>>(Wk, wh + 1 * NM * NM, wl + 1 * NM * NM);
    conv_split<<<NM * NM / 1024, 256>>>(Wv, wh + 2 * NM * NM, wl + 2 * NM * NM);
    conv_split<<<NM * NM / 1024, 256>>>(Wo, wh + 3 * NM * NM, wl + 3 * NM * NM);
    conv_mask<<<BATCH * SEQ * SEQ / 1024, 256>>>(mask, mbp);

    // ---- QKV projections ----
    cudaFuncSetAttribute(gemm_mma2,
                         cudaFuncAttributeMaxDynamicSharedMemorySize, GSMEM);
    dim3 gblock(256);
    dim3 ggrid(NM / 128, ROWS / 128);
    gemm_mma2<<<ggrid, gblock, GSMEM>>>(xh, xl, wh + 0 * NM * NM, wl + 0 * NM * NM,
                                        bq, nullptr, qh, ql, 0);
    gemm_mma2<<<ggrid, gblock, GSMEM>>>(xh, xl, wh + 1 * NM * NM, wl + 1 * NM * NM,
                                        bk, nullptr, kh, kl, 0);
    gemm_mma2<<<ggrid, gblock, GSMEM>>>(xh, xl, wh + 2 * NM * NM, wl + 2 * NM * NM,
                                        bv, nullptr, vh, vl, 0);

    // ---- attention ----
    const int asmem = 6 * ABUF;
    cudaFuncSetAttribute(attn_mma2,
                         cudaFuncAttributeMaxDynamicSharedMemorySize, asmem);
    dim3 agrid(SEQ / 128, NH, BATCH);
    attn_mma2<<<agrid, 256, asmem>>>(qh, ql, kh, kl, vh, vl, mbp, ch, cl);

    // ---- output projection ----
    gemm_mma2<<<ggrid, gblock, GSMEM>>>(ch, cl, wh + 3 * NM * NM, wl + 3 * NM * NM,
                                        bo, out, nullptr, nullptr, 1);
}

// round 8
// speedup vs baseline: 5.9616x; 2.1407x over previous
#include <cuda_runtime.h>
#include <cuda_bf16.h>
#include <cuda_fp16.h>
#include <math.h>
#include <stdint.h>

// Problem constants
#define NM 1024
#define NH 16
#define ND 64
#define BATCH 4
#define SEQ 1024
#define ROWS (BATCH*SEQ)   // 4096

// ---------------------------------------------------------------------------
// Scratch (device globals; no allocation allowed)
// ---------------------------------------------------------------------------
__device__ __half g_x[ROWS * NM];
__device__ __half g_w[4][NM * NM];
__device__ __half g_q[ROWS * NM];
__device__ __half g_k[ROWS * NM];
__device__ __half g_v[ROWS * NM];
__device__ __half g_c[ROWS * NM];
__device__ __nv_bfloat16 g_mb[BATCH * SEQ * SEQ];

// ===========================================================================
// Helpers
// ===========================================================================
__device__ __forceinline__ uint32_t smem_u32(const void* p) {
    uint32_t a;
    asm("{ .reg .u64 t; cvta.to.shared.u64 t, %1; cvt.u32.u64 %0, t; }"
        : "=r"(a) : "l"(p));
    return a;
}
__device__ __forceinline__ void cp16(uint32_t dst, const void* src) {
    asm volatile("cp.async.cg.shared.global [%0], [%1], 16;"
                 :: "r"(dst), "l"(src));
}
__device__ __forceinline__ void cp_commit() {
    asm volatile("cp.async.commit_group;");
}
template<int N> __device__ __forceinline__ void cp_wait() {
    asm volatile("cp.async.wait_group %0;" :: "n"(N));
}
__device__ __forceinline__ void ldm_x4(uint32_t* r, uint32_t a) {
    asm volatile("ldmatrix.sync.aligned.m8n8.x4.shared.b16 {%0,%1,%2,%3}, [%4];"
                 : "=r"(r[0]), "=r"(r[1]), "=r"(r[2]), "=r"(r[3]) : "r"(a));
}
__device__ __forceinline__ void ldm_x4t(uint32_t* r, uint32_t a) {
    asm volatile("ldmatrix.sync.aligned.m8n8.x4.trans.shared.b16 {%0,%1,%2,%3}, [%4];"
                 : "=r"(r[0]), "=r"(r[1]), "=r"(r[2]), "=r"(r[3]) : "r"(a));
}
__device__ __forceinline__ void ldm_x2(uint32_t* r, uint32_t a) {
    asm volatile("ldmatrix.sync.aligned.m8n8.x2.shared.b16 {%0,%1}, [%2];"
                 : "=r"(r[0]), "=r"(r[1]) : "r"(a));
}
__device__ __forceinline__ void mma_f16(float* c, const uint32_t* a,
                                        const uint32_t* b) {
    asm volatile(
        "mma.sync.aligned.m16n8k16.row.col.f32.f16.f16.f32 "
        "{%0,%1,%2,%3}, {%4,%5,%6,%7}, {%8,%9}, {%0,%1,%2,%3};"
        : "+f"(c[0]), "+f"(c[1]), "+f"(c[2]), "+f"(c[3])
        : "r"(a[0]), "r"(a[1]), "r"(a[2]), "r"(a[3]), "r"(b[0]), "r"(b[1]));
}
__device__ __forceinline__ uint32_t packh2(float x, float y) {
    __half2 h = __floats2half2_rn(x, y);
    return reinterpret_cast<uint32_t&>(h);
}

// ===========================================================================
// Conversion kernels (one-time)
// ===========================================================================
__global__ void conv_half(const float* __restrict__ in,
                          __half* __restrict__ out)
{
    int i = (blockIdx.x * 256 + threadIdx.x) * 4;
    float4 a = *(const float4*)(in + i);
    uint2 o;
    o.x = packh2(a.x, a.y);
    o.y = packh2(a.z, a.w);
    *(uint2*)(out + i) = o;
}

__global__ void conv_mask(const int* __restrict__ m,
                          __nv_bfloat16* __restrict__ mb)
{
    int i = (blockIdx.x * 256 + threadIdx.x) * 4;
    int4 a = *(const int4*)(m + i);
    float f0 = (float)(a.x - 1) * 1e9f;
    float f1 = (float)(a.y - 1) * 1e9f;
    float f2 = (float)(a.z - 1) * 1e9f;
    float f3 = (float)(a.w - 1) * 1e9f;
    __nv_bfloat162 p0 = __floats2bfloat162_rn(f0, f1);
    __nv_bfloat162 p1 = __floats2bfloat162_rn(f2, f3);
    uint2 o;
    o.x = reinterpret_cast<uint32_t&>(p0);
    o.y = reinterpret_cast<uint32_t&>(p1);
    *(uint2*)(mb + i) = o;
}

// ===========================================================================
// fp16 single-pass GEMM: C[m][n] = sum_k A[m][k]*W[n][k] + bias[n]
// CTA 128x128, BK=64, 2-stage cp.async, 8 warps (2x4), each 64x32.
// mode 0: fp16 output Ch ; mode 1: fp32 output Cf.
// ===========================================================================
#define BKP 72                     // padded K stride (fp16 elems), 144 B
#define ASZH (128 * BKP * 2)       // 18432 bytes per array
#define SSTG (2 * ASZH)            // 36864 per stage
#define GSMEM (2 * SSTG)           // 73728

__global__ __launch_bounds__(256, 2)
void gemm_h(const __half* __restrict__ A_g,
            const __half* __restrict__ B_g,
            const float* __restrict__ bias,
            float* __restrict__ Cf,
            __half* __restrict__ Ch,
            int mode)
{
    extern __shared__ __align__(16) char smg[];
    const uint32_t sb = smem_u32(smg);

    const int tid  = threadIdx.x;
    const int lane = tid & 31;
    const int wid  = tid >> 5;
    const int wm   = (wid >> 2) * 64;
    const int wn   = (wid & 3) * 32;
    const int m0   = blockIdx.y * 128;
    const int n0   = blockIdx.x * 128;

    const __half* gsrc[2] = { A_g + (size_t)m0 * 1024, B_g + (size_t)n0 * 1024 };

    const uint32_t a_off = ((wm + (lane & 15)) * BKP + (lane >> 4) * 8) * 2;
    const uint32_t b_off = ((wn + (lane & 7)) * BKP + ((lane >> 3) & 1) * 8) * 2;

    float acc[4][4][4];
#pragma unroll
    for (int i = 0; i < 4; i++)
#pragma unroll
        for (int j = 0; j < 4; j++)
#pragma unroll
            for (int r = 0; r < 4; r++) acc[i][j][r] = 0.0f;

#define GLOAD(stg, kc) do {                                                  \
    uint32_t _sbase = sb + (stg) * SSTG;                                     \
    _Pragma("unroll")                                                        \
    for (int j = 0; j < 8; j++) {                                            \
        int arr = j >> 2;                                                    \
        int w   = tid + (j & 3) * 256;                                       \
        int row = w >> 3;                                                    \
        int c8  = (w & 7) * 8;                                               \
        cp16(_sbase + arr * ASZH + (uint32_t)(row * BKP + c8) * 2,           \
             gsrc[arr] + (size_t)row * 1024 + (kc) + c8);                    \
    } } while (0)

    GLOAD(0, 0);
    cp_commit();

    for (int kc = 0; kc < 16; kc++) {
        int s = kc & 1;
        if (kc < 15) {
            GLOAD(s ^ 1, (kc + 1) * 64);
            cp_commit();
            cp_wait<1>();
        } else {
            cp_wait<0>();
        }
        __syncthreads();

        const uint32_t sA = sb + s * SSTG;
        const uint32_t sB = sA + ASZH;

#pragma unroll
        for (int ks = 0; ks < 4; ks++) {
            const uint32_t kb = ks * 32;   // 16 halfs = 32 bytes

            uint32_t af[4][4];
#pragma unroll
            for (int tm = 0; tm < 4; tm++)
                ldm_x4(af[tm], sA + a_off + kb + tm * (16 * BKP * 2));

            uint32_t bf[4][2];
#pragma unroll
            for (int tn = 0; tn < 4; tn++)
                ldm_x2(bf[tn], sB + b_off + kb + tn * (8 * BKP * 2));

#pragma unroll
            for (int tm = 0; tm < 4; tm++)
#pragma unroll
                for (int tn = 0; tn < 4; tn++)
                    mma_f16(acc[tm][tn], af[tm], bf[tn]);
        }
        __syncthreads();
    }
#undef GLOAD

    // ---- epilogue ----
    const int qr = lane >> 2;
    const int qc = (lane & 3) * 2;
    if (mode == 0) {
#pragma unroll
        for (int tm = 0; tm < 4; tm++) {
            int row = m0 + wm + tm * 16 + qr;
#pragma unroll
            for (int tn = 0; tn < 4; tn++) {
                int col = n0 + wn + tn * 8 + qc;
                float b0 = bias[col], b1 = bias[col + 1];
                *(uint32_t*)(Ch + (size_t)row * 1024 + col) =
                    packh2(acc[tm][tn][0] + b0, acc[tm][tn][1] + b1);
                *(uint32_t*)(Ch + (size_t)(row + 8) * 1024 + col) =
                    packh2(acc[tm][tn][2] + b0, acc[tm][tn][3] + b1);
            }
        }
    } else {
#pragma unroll
        for (int tm = 0; tm < 4; tm++) {
            int row = m0 + wm + tm * 16 + qr;
#pragma unroll
            for (int tn = 0; tn < 4; tn++) {
                int col = n0 + wn + tn * 8 + qc;
                float b0 = bias[col], b1 = bias[col + 1];
                *(float2*)(Cf + (size_t)row * 1024 + col) =
                    make_float2(acc[tm][tn][0] + b0, acc[tm][tn][1] + b1);
                *(float2*)(Cf + (size_t)(row + 8) * 1024 + col) =
                    make_float2(acc[tm][tn][2] + b0, acc[tm][tn][3] + b1);
            }
        }
    }
}

// ===========================================================================
// fp16 tensor-core flash attention. CTA: 128 q-rows x one head, 8 warps.
// ===========================================================================
#define ALD 72
#define ABUF (128 * ALD * 2)   // 18432 bytes per buffer

__global__ __launch_bounds__(256)
void attn_h(const __half* __restrict__ q, const __half* __restrict__ k,
            const __half* __restrict__ v, const __nv_bfloat16* __restrict__ mb,
            __half* __restrict__ ctx)
{
    extern __shared__ __align__(16) char sma[];
    const uint32_t sQ = smem_u32(sma);
    const uint32_t sK = sQ + ABUF;
    const uint32_t sV = sQ + 2 * ABUF;

    const int tid  = threadIdx.x;
    const int lane = tid & 31;
    const int wid  = tid >> 5;
    const int q0   = blockIdx.x * 128;
    const int h    = blockIdx.y;
    const int b    = blockIdx.z;

    const size_t base  = (size_t)b * SEQ * NM + (size_t)h * ND;
    const size_t mbase = (size_t)b * SEQ * SEQ;

    // ---- Q tile (cp.async) ----
#pragma unroll
    for (int j = 0; j < 4; j++) {
        int w   = tid + j * 256;
        int row = w >> 3;
        int c8  = (w & 7) * 8;
        cp16(sQ + (uint32_t)(row * ALD + c8) * 2,
             q + base + (size_t)(q0 + row) * 1024 + c8);
    }
    cp_commit();
    cp_wait<0>();
    __syncthreads();

    // ---- persistent Q fragments ----
    uint32_t qf[4][4];
    {
        uint32_t qo = ((wid * 16 + (lane & 15)) * ALD + (lane >> 4) * 8) * 2;
#pragma unroll
        for (int ks = 0; ks < 4; ks++)
            ldm_x4(qf[ks], sQ + qo + ks * 32);
    }

    float oacc[8][4];
#pragma unroll
    for (int i = 0; i < 8; i++)
#pragma unroll
        for (int r = 0; r < 4; r++) oacc[i][r] = 0.0f;
    float mr1 = -INFINITY, mr2 = -INFINITY, lr1 = 0.0f, lr2 = 0.0f;

    const float SCALE = 0.03125f;
    const int r1 = wid * 16 + (lane >> 2);

    const uint32_t koff = ((lane & 7) * ALD + ((lane >> 3) & 3) * 8) * 2;
    const uint32_t voff = (((lane & 7) + 8 * ((lane >> 3) & 1)) * ALD) * 2
                        + ((lane >> 4) & 1) * 16;

    const __half* ksrc[2] = { k + base, v + base };
    const uint32_t kdst[2] = { sK, sV };

    for (int t = 0; t < 8; t++) {
        const int k0 = t * 128;
        // ---- K/V tiles ----
#pragma unroll
        for (int j = 0; j < 8; j++) {
            int arr = j >> 2;
            int w   = tid + (j & 3) * 256;
            int row = w >> 3;
            int c8  = (w & 7) * 8;
            cp16(kdst[arr] + (uint32_t)(row * ALD + c8) * 2,
                 ksrc[arr] + (size_t)(k0 + row) * 1024 + c8);
        }
        cp_commit();
        cp_wait<0>();
        __syncthreads();

        // ---- S = Q K^T ----
        float sacc[16][4];
#pragma unroll
        for (int j = 0; j < 16; j++) {
#pragma unroll
            for (int r = 0; r < 4; r++) sacc[j][r] = 0.0f;
            uint32_t ka = koff + (uint32_t)(j * 8 * ALD * 2);
            uint32_t kf[8];
            ldm_x4(kf,     sK + ka);
            ldm_x4(kf + 4, sK + ka + 64);
#pragma unroll
            for (int ks = 0; ks < 4; ks++)
                mma_f16(sacc[j], qf[ks], &kf[ks * 2]);
        }

        // ---- mask + scale + row max ----
        const __nv_bfloat16* mp =
            mb + mbase + (size_t)(q0 + r1) * SEQ + k0 + (lane & 3) * 2;
        float rmax1 = -INFINITY, rmax2 = -INFINITY;
#pragma unroll
        for (int j = 0; j < 16; j++) {
            uint32_t ma = *(const uint32_t*)(mp + j * 8);
            uint32_t mc = *(const uint32_t*)(mp + 8 * SEQ + j * 8);
            float2 f1 = __bfloat1622float2(reinterpret_cast<__nv_bfloat162&>(ma));
            float2 f2 = __bfloat1622float2(reinterpret_cast<__nv_bfloat162&>(mc));
            sacc[j][0] = sacc[j][0] * SCALE + f1.x;
            sacc[j][1] = sacc[j][1] * SCALE + f1.y;
            sacc[j][2] = sacc[j][2] * SCALE + f2.x;
            sacc[j][3] = sacc[j][3] * SCALE + f2.y;
            rmax1 = fmaxf(rmax1, fmaxf(sacc[j][0], sacc[j][1]));
            rmax2 = fmaxf(rmax2, fmaxf(sacc[j][2], sacc[j][3]));
        }
#pragma unroll
        for (int off = 1; off < 4; off <<= 1) {
            rmax1 = fmaxf(rmax1, __shfl_xor_sync(0xffffffffu, rmax1, off));
            rmax2 = fmaxf(rmax2, __shfl_xor_sync(0xffffffffu, rmax2, off));
        }

        // ---- online softmax ----
        float mn1 = fmaxf(mr1, rmax1);
        float mn2 = fmaxf(mr2, rmax2);
        float c1 = __expf(mr1 - mn1);
        float c2 = __expf(mr2 - mn2);
        mr1 = mn1; mr2 = mn2;
#pragma unroll
        for (int i = 0; i < 8; i++) {
            oacc[i][0] *= c1; oacc[i][1] *= c1;
            oacc[i][2] *= c2; oacc[i][3] *= c2;
        }
        float rs1 = 0.0f, rs2 = 0.0f;
#pragma unroll
        for (int j = 0; j < 16; j++) {
            sacc[j][0] = __expf(sacc[j][0] - mn1);
            sacc[j][1] = __expf(sacc[j][1] - mn1);
            sacc[j][2] = __expf(sacc[j][2] - mn2);
            sacc[j][3] = __expf(sacc[j][3] - mn2);
            rs1 += sacc[j][0] + sacc[j][1];
            rs2 += sacc[j][2] + sacc[j][3];
        }
#pragma unroll
        for (int off = 1; off < 4; off <<= 1) {
            rs1 += __shfl_xor_sync(0xffffffffu, rs1, off);
            rs2 += __shfl_xor_sync(0xffffffffu, rs2, off);
        }
        lr1 = lr1 * c1 + rs1;
        lr2 = lr2 * c2 + rs2;

        // ---- O += P V ----
#pragma unroll
        for (int ks = 0; ks < 8; ks++) {
            uint32_t ph[4];
            ph[0] = packh2(sacc[2*ks][0],   sacc[2*ks][1]);
            ph[1] = packh2(sacc[2*ks][2],   sacc[2*ks][3]);
            ph[2] = packh2(sacc[2*ks+1][0], sacc[2*ks+1][1]);
            ph[3] = packh2(sacc[2*ks+1][2], sacc[2*ks+1][3]);

            uint32_t va = voff + (uint32_t)(ks * 16 * ALD * 2);
#pragma unroll
            for (int tp = 0; tp < 4; tp++) {
                uint32_t vf[4];
                ldm_x4t(vf, sV + va + tp * 32);
                mma_f16(oacc[2*tp],   ph, &vf[0]);
                mma_f16(oacc[2*tp+1], ph, &vf[2]);
            }
        }
        __syncthreads();
    }

    // ---- normalize + store ctx (fp16) ----
    float i1 = 1.0f / lr1, i2 = 1.0f / lr2;
    size_t off0 = base + (size_t)(q0 + r1) * NM + (lane & 3) * 2;
#pragma unroll
    for (int tn = 0; tn < 8; tn++) {
        *(uint32_t*)(ctx + off0 + tn * 8) =
            packh2(oacc[tn][0] * i1, oacc[tn][1] * i1);
        *(uint32_t*)(ctx + off0 + 8 * NM + tn * 8) =
            packh2(oacc[tn][2] * i2, oacc[tn][3] * i2);
    }
}

// ---------------------------------------------------------------------------
// kernel_launch — inputs: x, mask, Wq, bq, Wk, bk, Wv, bv, Wo, bo
// ---------------------------------------------------------------------------
extern "C" void kernel_launch(void* const* d_in, const int* in_sizes, int n_in,
                              void* d_out, int out_size)
{
    const float* x    = (const float*)d_in[0];
    const int*   mask = (const int*)  d_in[1];
    const float* Wq   = (const float*)d_in[2];
    const float* bq   = (const float*)d_in[3];
    const float* Wk   = (const float*)d_in[4];
    const float* bk   = (const float*)d_in[5];
    const float* Wv   = (const float*)d_in[6];
    const float* bv   = (const float*)d_in[7];
    const float* Wo   = (const float*)d_in[8];
    const float* bo   = (const float*)d_in[9];
    float* out = (float*)d_out;

    __half *xp, *wp, *qp, *kp, *vp, *cp;
    __nv_bfloat16* mbp;
    cudaGetSymbolAddress((void**)&xp, g_x);
    cudaGetSymbolAddress((void**)&wp, g_w);
    cudaGetSymbolAddress((void**)&qp, g_q);
    cudaGetSymbolAddress((void**)&kp, g_k);
    cudaGetSymbolAddress((void**)&vp, g_v);
    cudaGetSymbolAddress((void**)&cp, g_c);
    cudaGetSymbolAddress((void**)&mbp, g_mb);

    // ---- conversions ----
    conv_half<<<ROWS * NM / 1024, 256>>>(x, xp);
    conv_half<<<NM * NM / 1024, 256>>>(Wq, wp + 0 * NM * NM);
    conv_half<<<NM * NM / 1024, 256>>>(Wk, wp + 1 * NM * NM);
    conv_half<<<NM * NM / 1024, 256>>>(Wv, wp + 2 * NM * NM);
    conv_half<<<NM * NM / 1024, 256>>>(Wo, wp + 3 * NM * NM);
    conv_mask<<<BATCH * SEQ * SEQ / 1024, 256>>>(mask, mbp);

    // ---- QKV projections ----
    cudaFuncSetAttribute(gemm_h,
                         cudaFuncAttributeMaxDynamicSharedMemorySize, GSMEM);
    dim3 gblock(256);
    dim3 ggrid(NM / 128, ROWS / 128);
    gemm_h<<<ggrid, gblock, GSMEM>>>(xp, wp + 0 * NM * NM, bq, nullptr, qp, 0);
    gemm_h<<<ggrid, gblock, GSMEM>>>(xp, wp + 1 * NM * NM, bk, nullptr, kp, 0);
    gemm_h<<<ggrid, gblock, GSMEM>>>(xp, wp + 2 * NM * NM, bv, nullptr, vp, 0);

    // ---- attention ----
    const int asmem = 3 * ABUF;   // 55296
    cudaFuncSetAttribute(attn_h,
                         cudaFuncAttributeMaxDynamicSharedMemorySize, asmem);
    dim3 agrid(SEQ / 128, NH, BATCH);
    attn_h<<<agrid, 256, asmem>>>(qp, kp, vp, mbp, cp);

    // ---- output projection ----
    gemm_h<<<ggrid, gblock, GSMEM>>>(cp, wp + 3 * NM * NM, bo, out, nullptr, 1);
}

// round 9
// speedup vs baseline: 6.4521x; 1.0823x over previous
#include <cuda_runtime.h>
#include <cuda_bf16.h>
#include <cuda_fp16.h>
#include <math.h>
#include <stdint.h>

// Problem constants
#define NM 1024
#define NH 16
#define ND 64
#define BATCH 4
#define SEQ 1024
#define ROWS (BATCH*SEQ)   // 4096

// ---------------------------------------------------------------------------
// Scratch (device globals; no allocation allowed)
// ---------------------------------------------------------------------------
__device__ __half g_x[ROWS * NM];
__device__ __half g_w[4][NM * NM];
__device__ __half g_q[ROWS * NM];
__device__ __half g_k[ROWS * NM];
__device__ __half g_v[ROWS * NM];
__device__ __half g_c[ROWS * NM];
__device__ __nv_bfloat16 g_mb[BATCH * SEQ * SEQ];

// ===========================================================================
// Helpers
// ===========================================================================
__device__ __forceinline__ uint32_t smem_u32(const void* p) {
    uint32_t a;
    asm("{ .reg .u64 t; cvta.to.shared.u64 t, %1; cvt.u32.u64 %0, t; }"
        : "=r"(a) : "l"(p));
    return a;
}
__device__ __forceinline__ void cp16(uint32_t dst, const void* src) {
    asm volatile("cp.async.cg.shared.global [%0], [%1], 16;"
                 :: "r"(dst), "l"(src));
}
__device__ __forceinline__ void cp_commit() {
    asm volatile("cp.async.commit_group;");
}
template<int N> __device__ __forceinline__ void cp_wait() {
    asm volatile("cp.async.wait_group %0;" :: "n"(N));
}
__device__ __forceinline__ void ldm_x4(uint32_t* r, uint32_t a) {
    asm volatile("ldmatrix.sync.aligned.m8n8.x4.shared.b16 {%0,%1,%2,%3}, [%4];"
                 : "=r"(r[0]), "=r"(r[1]), "=r"(r[2]), "=r"(r[3]) : "r"(a));
}
__device__ __forceinline__ void ldm_x4t(uint32_t* r, uint32_t a) {
    asm volatile("ldmatrix.sync.aligned.m8n8.x4.trans.shared.b16 {%0,%1,%2,%3}, [%4];"
                 : "=r"(r[0]), "=r"(r[1]), "=r"(r[2]), "=r"(r[3]) : "r"(a));
}
__device__ __forceinline__ void ldm_x2(uint32_t* r, uint32_t a) {
    asm volatile("ldmatrix.sync.aligned.m8n8.x2.shared.b16 {%0,%1}, [%2];"
                 : "=r"(r[0]), "=r"(r[1]) : "r"(a));
}
__device__ __forceinline__ void mma_f16(float* c, const uint32_t* a,
                                        const uint32_t* b) {
    asm volatile(
        "mma.sync.aligned.m16n8k16.row.col.f32.f16.f16.f32 "
        "{%0,%1,%2,%3}, {%4,%5,%6,%7}, {%8,%9}, {%0,%1,%2,%3};"
        : "+f"(c[0]), "+f"(c[1]), "+f"(c[2]), "+f"(c[3])
        : "r"(a[0]), "r"(a[1]), "r"(a[2]), "r"(a[3]), "r"(b[0]), "r"(b[1]));
}
__device__ __forceinline__ uint32_t packh2(float x, float y) {
    __half2 h = __floats2half2_rn(x, y);
    return reinterpret_cast<uint32_t&>(h);
}

// ===========================================================================
// Conversion kernels (one-time)
// ===========================================================================
__global__ void conv_half(const float* __restrict__ in,
                          __half* __restrict__ out)
{
    int i = (blockIdx.x * 256 + threadIdx.x) * 4;
    float4 a = *(const float4*)(in + i);
    uint2 o;
    o.x = packh2(a.x, a.y);
    o.y = packh2(a.z, a.w);
    *(uint2*)(out + i) = o;
}

// all 4 weights in one launch (grid.z selects source)
__global__ void conv_w4(const float* __restrict__ w0, const float* __restrict__ w1,
                        const float* __restrict__ w2, const float* __restrict__ w3,
                        __half* __restrict__ out)
{
    int z = blockIdx.z;
    const float* src = (z == 0) ? w0 : (z == 1) ? w1 : (z == 2) ? w2 : w3;
    int i = (blockIdx.x * 256 + threadIdx.x) * 4;
    float4 a = *(const float4*)(src + i);
    uint2 o;
    o.x = packh2(a.x, a.y);
    o.y = packh2(a.z, a.w);
    *(uint2*)(out + (size_t)z * NM * NM + i) = o;
}

__global__ void conv_mask(const int* __restrict__ m,
                          __nv_bfloat16* __restrict__ mb)
{
    int i = (blockIdx.x * 256 + threadIdx.x) * 4;
    int4 a = *(const int4*)(m + i);
    float f0 = (float)(a.x - 1) * 1e9f;
    float f1 = (float)(a.y - 1) * 1e9f;
    float f2 = (float)(a.z - 1) * 1e9f;
    float f3 = (float)(a.w - 1) * 1e9f;
    __nv_bfloat162 p0 = __floats2bfloat162_rn(f0, f1);
    __nv_bfloat162 p1 = __floats2bfloat162_rn(f2, f3);
    uint2 o;
    o.x = reinterpret_cast<uint32_t&>(p0);
    o.y = reinterpret_cast<uint32_t&>(p1);
    *(uint2*)(mb + i) = o;
}

// ===========================================================================
// fp16 GEMM core (CTA 128x128, BK=64, 2-stage cp.async, 8 warps)
// ===========================================================================
#define BKP 72                     // padded K stride (fp16 elems), 144 B
#define ASZH (128 * BKP * 2)       // 18432 bytes per array
#define SSTG (2 * ASZH)            // 36864 per stage
#define GSMEM (2 * SSTG)           // 73728

struct GemmOut { float acc[4][4][4]; };

__device__ __forceinline__ void gemm_core(
    const __half* __restrict__ A_g, const __half* __restrict__ B_g,
    uint32_t sb, int tid, float acc[4][4][4])
{
    const int lane = tid & 31;
    const int wid  = tid >> 5;
    const int wm   = (wid >> 2) * 64;
    const int wn   = (wid & 3) * 32;

    const __half* gsrc[2] = { A_g, B_g };

    const uint32_t a_off = ((wm + (lane & 15)) * BKP + (lane >> 4) * 8) * 2;
    const uint32_t b_off = ((wn + (lane & 7)) * BKP + ((lane >> 3) & 1) * 8) * 2;

#pragma unroll
    for (int i = 0; i < 4; i++)
#pragma unroll
        for (int j = 0; j < 4; j++)
#pragma unroll
            for (int r = 0; r < 4; r++) acc[i][j][r] = 0.0f;

#define GLOAD(stg, kc) do {                                                  \
    uint32_t _sbase = sb + (stg) * SSTG;                                     \
    _Pragma("unroll")                                                        \
    for (int j = 0; j < 8; j++) {                                            \
        int arr = j >> 2;                                                    \
        int w   = tid + (j & 3) * 256;                                       \
        int row = w >> 3;                                                    \
        int c8  = (w & 7) * 8;                                               \
        cp16(_sbase + arr * ASZH + (uint32_t)(row * BKP + c8) * 2,           \
             gsrc[arr] + (size_t)row * 1024 + (kc) + c8);                    \
    } } while (0)

    GLOAD(0, 0);
    cp_commit();

    for (int kc = 0; kc < 16; kc++) {
        int s = kc & 1;
        if (kc < 15) {
            GLOAD(s ^ 1, (kc + 1) * 64);
            cp_commit();
            cp_wait<1>();
        } else {
            cp_wait<0>();
        }
        __syncthreads();

        const uint32_t sA = sb + s * SSTG;
        const uint32_t sB = sA + ASZH;

#pragma unroll
        for (int ks = 0; ks < 4; ks++) {
            const uint32_t kb = ks * 32;

            uint32_t af[4][4];
#pragma unroll
            for (int tm = 0; tm < 4; tm++)
                ldm_x4(af[tm], sA + a_off + kb + tm * (16 * BKP * 2));

            uint32_t bf[4][2];
#pragma unroll
            for (int tn = 0; tn < 4; tn++)
                ldm_x2(bf[tn], sB + b_off + kb + tn * (8 * BKP * 2));

#pragma unroll
            for (int tm = 0; tm < 4; tm++)
#pragma unroll
                for (int tn = 0; tn < 4; tn++)
                    mma_f16(acc[tm][tn], af[tm], bf[tn]);
        }
        __syncthreads();
    }
#undef GLOAD
}

// ---- fused QKV projection: grid (8, 32, 3) ----
__global__ __launch_bounds__(256, 2)
void gemm_qkv(const __half* __restrict__ X, const __half* __restrict__ W,
              const float* __restrict__ bq, const float* __restrict__ bk,
              const float* __restrict__ bv,
              __half* __restrict__ Q, __half* __restrict__ K,
              __half* __restrict__ V)
{
    extern __shared__ __align__(16) char smg[];
    const uint32_t sb = smem_u32(smg);
    const int tid = threadIdx.x;
    const int m0  = blockIdx.y * 128;
    const int n0  = blockIdx.x * 128;
    const int z   = blockIdx.z;

    const __half* Wz   = W + (size_t)z * NM * NM;
    const float*  bias = (z == 0) ? bq : (z == 1) ? bk : bv;
    __half*       Out  = (z == 0) ? Q  : (z == 1) ? K  : V;

    float acc[4][4][4];
    gemm_core(X + (size_t)m0 * 1024, Wz + (size_t)n0 * 1024, sb, tid, acc);

    const int lane = tid & 31;
    const int wid  = tid >> 5;
    const int wm   = (wid >> 2) * 64;
    const int wn   = (wid & 3) * 32;
    const int qr   = lane >> 2;
    const int qc   = (lane & 3) * 2;
#pragma unroll
    for (int tm = 0; tm < 4; tm++) {
        int row = m0 + wm + tm * 16 + qr;
#pragma unroll
        for (int tn = 0; tn < 4; tn++) {
            int col = n0 + wn + tn * 8 + qc;
            float b0 = bias[col], b1 = bias[col + 1];
            *(uint32_t*)(Out + (size_t)row * 1024 + col) =
                packh2(acc[tm][tn][0] + b0, acc[tm][tn][1] + b1);
            *(uint32_t*)(Out + (size_t)(row + 8) * 1024 + col) =
                packh2(acc[tm][tn][2] + b0, acc[tm][tn][3] + b1);
        }
    }
}

// ---- output projection (fp32 out) ----
__global__ __launch_bounds__(256, 2)
void gemm_o(const __half* __restrict__ A_g, const __half* __restrict__ B_g,
            const float* __restrict__ bias, float* __restrict__ Cf)
{
    extern __shared__ __align__(16) char smg[];
    const uint32_t sb = smem_u32(smg);
    const int tid = threadIdx.x;
    const int m0  = blockIdx.y * 128;
    const int n0  = blockIdx.x * 128;

    float acc[4][4][4];
    gemm_core(A_g + (size_t)m0 * 1024, B_g + (size_t)n0 * 1024, sb, tid, acc);

    const int lane = tid & 31;
    const int wid  = tid >> 5;
    const int wm   = (wid >> 2) * 64;
    const int wn   = (wid & 3) * 32;
    const int qr   = lane >> 2;
    const int qc   = (lane & 3) * 2;
#pragma unroll
    for (int tm = 0; tm < 4; tm++) {
        int row = m0 + wm + tm * 16 + qr;
#pragma unroll
        for (int tn = 0; tn < 4; tn++) {
            int col = n0 + wn + tn * 8 + qc;
            float b0 = bias[col], b1 = bias[col + 1];
            *(float2*)(Cf + (size_t)row * 1024 + col) =
                make_float2(acc[tm][tn][0] + b0, acc[tm][tn][1] + b1);
            *(float2*)(Cf + (size_t)(row + 8) * 1024 + col) =
                make_float2(acc[tm][tn][2] + b0, acc[tm][tn][3] + b1);
        }
    }
}

// ===========================================================================
// fp16 flash attention with double-buffered K/V (loads overlap compute).
// CTA: 128 q-rows x one head, 8 warps. smem: Q + 2x(K,V) = 5 buffers.
// ===========================================================================
#define ALD 72
#define ABUF (128 * ALD * 2)   // 18432 bytes per buffer

__global__ __launch_bounds__(256)
void attn_h(const __half* __restrict__ q, const __half* __restrict__ k,
            const __half* __restrict__ v, const __nv_bfloat16* __restrict__ mb,
            __half* __restrict__ ctx)
{
    extern __shared__ __align__(16) char sma[];
    const uint32_t sQ  = smem_u32(sma);
    const uint32_t sK0 = sQ + ABUF;
    const uint32_t sV0 = sQ + 2 * ABUF;
    const uint32_t sK1 = sQ + 3 * ABUF;
    const uint32_t sV1 = sQ + 4 * ABUF;

    const int tid  = threadIdx.x;
    const int lane = tid & 31;
    const int wid  = tid >> 5;
    const int q0   = blockIdx.x * 128;
    const int h    = blockIdx.y;
    const int b    = blockIdx.z;

    const size_t base  = (size_t)b * SEQ * NM + (size_t)h * ND;
    const size_t mbase = (size_t)b * SEQ * SEQ;

    const __half* ksrc = k + base;
    const __half* vsrc = v + base;

#define KVLOAD(kbuf, vbuf, k0) do {                                          \
    _Pragma("unroll")                                                        \
    for (int j = 0; j < 8; j++) {                                            \
        int arr = j >> 2;                                                    \
        int w   = tid + (j & 3) * 256;                                       \
        int row = w >> 3;                                                    \
        int c8  = (w & 7) * 8;                                               \
        cp16((arr ? (vbuf) : (kbuf)) + (uint32_t)(row * ALD + c8) * 2,       \
             (arr ? vsrc : ksrc) + (size_t)((k0) + row) * 1024 + c8);        \
    }                                                                        \
    cp_commit(); } while (0)

    // ---- prologue: Q loads, then KV tile 0 ----
#pragma unroll
    for (int j = 0; j < 4; j++) {
        int w   = tid + j * 256;
        int row = w >> 3;
        int c8  = (w & 7) * 8;
        cp16(sQ + (uint32_t)(row * ALD + c8) * 2,
             q + base + (size_t)(q0 + row) * 1024 + c8);
    }
    cp_commit();
    KVLOAD(sK0, sV0, 0);

    cp_wait<1>();            // Q ready (KV0 may still be in flight)
    __syncthreads();

    uint32_t qf[4][4];
    {
        uint32_t qo = ((wid * 16 + (lane & 15)) * ALD + (lane >> 4) * 8) * 2;
#pragma unroll
        for (int ks = 0; ks < 4; ks++)
            ldm_x4(qf[ks], sQ + qo + ks * 32);
    }

    float oacc[8][4];
#pragma unroll
    for (int i = 0; i < 8; i++)
#pragma unroll
        for (int r = 0; r < 4; r++) oacc[i][r] = 0.0f;
    float mr1 = -INFINITY, mr2 = -INFINITY, lr1 = 0.0f, lr2 = 0.0f;

    const float SCALE = 0.03125f;
    const int r1 = wid * 16 + (lane >> 2);

    const uint32_t koff = ((lane & 7) * ALD + ((lane >> 3) & 3) * 8) * 2;
    const uint32_t voff = (((lane & 7) + 8 * ((lane >> 3) & 1)) * ALD) * 2
                        + ((lane >> 4) & 1) * 16;

    for (int t = 0; t < 8; t++) {
        cp_wait<0>();        // KV[t] ready
        __syncthreads();     // all warps done with buf[t^1], data visible

        const uint32_t sK = (t & 1) ? sK1 : sK0;
        const uint32_t sV = (t & 1) ? sV1 : sV0;
        if (t < 7) {
            // prefetch KV[t+1] into the other buffer; overlaps compute below
            if (t & 1) KVLOAD(sK0, sV0, (t + 1) * 128);
            else       KVLOAD(sK1, sV1, (t + 1) * 128);
        }
        const int k0 = t * 128;

        // ---- S = Q K^T ----
        float sacc[16][4];
#pragma unroll
        for (int j = 0; j < 16; j++) {
#pragma unroll
            for (int r = 0; r < 4; r++) sacc[j][r] = 0.0f;
            uint32_t ka = koff + (uint32_t)(j * 8 * ALD * 2);
            uint32_t kf[8];
            ldm_x4(kf,     sK + ka);
            ldm_x4(kf + 4, sK + ka + 64);
#pragma unroll
            for (int ks = 0; ks < 4; ks++)
                mma_f16(sacc[j], qf[ks], &kf[ks * 2]);
        }

        // ---- mask + scale + row max ----
        const __nv_bfloat16* mp =
            mb + mbase + (size_t)(q0 + r1) * SEQ + k0 + (lane & 3) * 2;
        float rmax1 = -INFINITY, rmax2 = -INFINITY;
#pragma unroll
        for (int j = 0; j < 16; j++) {
            uint32_t ma = *(const uint32_t*)(mp + j * 8);
            uint32_t mc = *(const uint32_t*)(mp + 8 * SEQ + j * 8);
            float2 f1 = __bfloat1622float2(reinterpret_cast<__nv_bfloat162&>(ma));
            float2 f2 = __bfloat1622float2(reinterpret_cast<__nv_bfloat162&>(mc));
            sacc[j][0] = sacc[j][0] * SCALE + f1.x;
            sacc[j][1] = sacc[j][1] * SCALE + f1.y;
            sacc[j][2] = sacc[j][2] * SCALE + f2.x;
            sacc[j][3] = sacc[j][3] * SCALE + f2.y;
            rmax1 = fmaxf(rmax1, fmaxf(sacc[j][0], sacc[j][1]));
            rmax2 = fmaxf(rmax2, fmaxf(sacc[j][2], sacc[j][3]));
        }
#pragma unroll
        for (int off = 1; off < 4; off <<= 1) {
            rmax1 = fmaxf(rmax1, __shfl_xor_sync(0xffffffffu, rmax1, off));
            rmax2 = fmaxf(rmax2, __shfl_xor_sync(0xffffffffu, rmax2, off));
        }

        // ---- online softmax ----
        float mn1 = fmaxf(mr1, rmax1);
        float mn2 = fmaxf(mr2, rmax2);
        float c1 = __expf(mr1 - mn1);
        float c2 = __expf(mr2 - mn2);
        mr1 = mn1; mr2 = mn2;
#pragma unroll
        for (int i = 0; i < 8; i++) {
            oacc[i][0] *= c1; oacc[i][1] *= c1;
            oacc[i][2] *= c2; oacc[i][3] *= c2;
        }
        float rs1 = 0.0f, rs2 = 0.0f;
#pragma unroll
        for (int j = 0; j < 16; j++) {
            sacc[j][0] = __expf(sacc[j][0] - mn1);
            sacc[j][1] = __expf(sacc[j][1] - mn1);
            sacc[j][2] = __expf(sacc[j][2] - mn2);
            sacc[j][3] = __expf(sacc[j][3] - mn2);
            rs1 += sacc[j][0] + sacc[j][1];
            rs2 += sacc[j][2] + sacc[j][3];
        }
#pragma unroll
        for (int off = 1; off < 4; off <<= 1) {
            rs1 += __shfl_xor_sync(0xffffffffu, rs1, off);
            rs2 += __shfl_xor_sync(0xffffffffu, rs2, off);
        }
        lr1 = lr1 * c1 + rs1;
        lr2 = lr2 * c2 + rs2;

        // ---- O += P V ----
#pragma unroll
        for (int ks = 0; ks < 8; ks++) {
            uint32_t ph[4];
            ph[0] = packh2(sacc[2*ks][0],   sacc[2*ks][1]);
            ph[1] = packh2(sacc[2*ks][2],   sacc[2*ks][3]);
            ph[2] = packh2(sacc[2*ks+1][0], sacc[2*ks+1][1]);
            ph[3] = packh2(sacc[2*ks+1][2], sacc[2*ks+1][3]);

            uint32_t va = voff + (uint32_t)(ks * 16 * ALD * 2);
#pragma unroll
            for (int tp = 0; tp < 4; tp++) {
                uint32_t vf[4];
                ldm_x4t(vf, sV + va + tp * 32);
                mma_f16(oacc[2*tp],   ph, &vf[0]);
                mma_f16(oacc[2*tp+1], ph, &vf[2]);
            }
        }
        // no trailing sync: next iteration's wait+sync protects buffer reuse
    }
#undef KVLOAD

    // ---- normalize + store ctx (fp16) ----
    float i1 = 1.0f / lr1, i2 = 1.0f / lr2;
    size_t off0 = base + (size_t)(q0 + r1) * NM + (lane & 3) * 2;
#pragma unroll
    for (int tn = 0; tn < 8; tn++) {
        *(uint32_t*)(ctx + off0 + tn * 8) =
            packh2(oacc[tn][0] * i1, oacc[tn][1] * i1);
        *(uint32_t*)(ctx + off0 + 8 * NM + tn * 8) =
            packh2(oacc[tn][2] * i2, oacc[tn][3] * i2);
    }
}

// ---------------------------------------------------------------------------
// kernel_launch — inputs: x, mask, Wq, bq, Wk, bk, Wv, bv, Wo, bo
// ---------------------------------------------------------------------------
extern "C" void kernel_launch(void* const* d_in, const int* in_sizes, int n_in,
                              void* d_out, int out_size)
{
    const float* x    = (const float*)d_in[0];
    const int*   mask = (const int*)  d_in[1];
    const float* Wq   = (const float*)d_in[2];
    const float* bq   = (const float*)d_in[3];
    const float* Wk   = (const float*)d_in[4];
    const float* bk   = (const float*)d_in[5];
    const float* Wv   = (const float*)d_in[6];
    const float* bv   = (const float*)d_in[7];
    const float* Wo   = (const float*)d_in[8];
    const float* bo   = (const float*)d_in[9];
    float* out = (float*)d_out;

    __half *xp, *wp, *qp, *kp, *vp, *cp;
    __nv_bfloat16* mbp;
    cudaGetSymbolAddress((void**)&xp, g_x);
    cudaGetSymbolAddress((void**)&wp, g_w);
    cudaGetSymbolAddress((void**)&qp, g_q);
    cudaGetSymbolAddress((void**)&kp, g_k);
    cudaGetSymbolAddress((void**)&vp, g_v);
    cudaGetSymbolAddress((void**)&cp, g_c);
    cudaGetSymbolAddress((void**)&mbp, g_mb);

    // ---- conversions ----
    conv_half<<<ROWS * NM / 1024, 256>>>(x, xp);
    dim3 wgrid(NM * NM / 1024, 1, 4);
    conv_w4<<<wgrid, 256>>>(Wq, Wk, Wv, Wo, wp);
    conv_mask<<<BATCH * SEQ * SEQ / 1024, 256>>>(mask, mbp);

    // ---- fused QKV projection ----
    cudaFuncSetAttribute(gemm_qkv,
                         cudaFuncAttributeMaxDynamicSharedMemorySize, GSMEM);
    cudaFuncSetAttribute(gemm_o,
                         cudaFuncAttributeMaxDynamicSharedMemorySize, GSMEM);
    dim3 gblock(256);
    dim3 qgrid(NM / 128, ROWS / 128, 3);   // (8, 32, 3)
    gemm_qkv<<<qgrid, gblock, GSMEM>>>(xp, wp, bq, bk, bv, qp, kp, vp);

    // ---- attention ----
    const int asmem = 5 * ABUF;   // 92160
    cudaFuncSetAttribute(attn_h,
                         cudaFuncAttributeMaxDynamicSharedMemorySize, asmem);
    dim3 agrid(SEQ / 128, NH, BATCH);
    attn_h<<<agrid, 256, asmem>>>(qp, kp, vp, mbp, cp);

    // ---- output projection ----
    dim3 ogrid(NM / 128, ROWS / 128);
    gemm_o<<<ogrid, gblock, GSMEM>>>(cp, wp + 3 * (size_t)NM * NM, bo, out);
}

// round 10
// speedup vs baseline: 6.6268x; 1.0271x over previous
#include <cuda_runtime.h>
#include <cuda_bf16.h>
#include <cuda_fp16.h>
#include <math.h>
#include <stdint.h>

// Problem constants
#define NM 1024
#define NH 16
#define ND 64
#define BATCH 4
#define SEQ 1024
#define ROWS (BATCH*SEQ)   // 4096

// ---------------------------------------------------------------------------
// Scratch (device globals; no allocation allowed)
// ---------------------------------------------------------------------------
__device__ __half g_x[ROWS * NM];
__device__ __half g_w[4][NM * NM];
__device__ __half g_q[ROWS * NM];
__device__ __half g_k[ROWS * NM];
__device__ __half g_v[ROWS * NM];
__device__ __half g_c[ROWS * NM];
__device__ __nv_bfloat16 g_mb[BATCH * SEQ * SEQ];

// ===========================================================================
// Helpers
// ===========================================================================
__device__ __forceinline__ uint32_t smem_u32(const void* p) {
    uint32_t a;
    asm("{ .reg .u64 t; cvta.to.shared.u64 t, %1; cvt.u32.u64 %0, t; }"
        : "=r"(a) : "l"(p));
    return a;
}
__device__ __forceinline__ void cp16(uint32_t dst, const void* src) {
    asm volatile("cp.async.cg.shared.global [%0], [%1], 16;"
                 :: "r"(dst), "l"(src));
}
__device__ __forceinline__ void cp_commit() {
    asm volatile("cp.async.commit_group;");
}
template<int N> __device__ __forceinline__ void cp_wait() {
    asm volatile("cp.async.wait_group %0;" :: "n"(N));
}
__device__ __forceinline__ void ldm_x4(uint32_t* r, uint32_t a) {
    asm volatile("ldmatrix.sync.aligned.m8n8.x4.shared.b16 {%0,%1,%2,%3}, [%4];"
                 : "=r"(r[0]), "=r"(r[1]), "=r"(r[2]), "=r"(r[3]) : "r"(a));
}
__device__ __forceinline__ void ldm_x4t(uint32_t* r, uint32_t a) {
    asm volatile("ldmatrix.sync.aligned.m8n8.x4.trans.shared.b16 {%0,%1,%2,%3}, [%4];"
                 : "=r"(r[0]), "=r"(r[1]), "=r"(r[2]), "=r"(r[3]) : "r"(a));
}
__device__ __forceinline__ void mma_f16(float* c, const uint32_t* a,
                                        const uint32_t* b) {
    asm volatile(
        "mma.sync.aligned.m16n8k16.row.col.f32.f16.f16.f32 "
        "{%0,%1,%2,%3}, {%4,%5,%6,%7}, {%8,%9}, {%0,%1,%2,%3};"
        : "+f"(c[0]), "+f"(c[1]), "+f"(c[2]), "+f"(c[3])
        : "r"(a[0]), "r"(a[1]), "r"(a[2]), "r"(a[3]), "r"(b[0]), "r"(b[1]));
}
__device__ __forceinline__ uint32_t packh2(float x, float y) {
    __half2 h = __floats2half2_rn(x, y);
    return reinterpret_cast<uint32_t&>(h);
}

// ===========================================================================
// Fused conversion kernel — grid (4096, 3): y=0 x, y=1 weights, y=2 mask
// ===========================================================================
__global__ void conv_all(const float* __restrict__ x,
                         const float* __restrict__ w0, const float* __restrict__ w1,
                         const float* __restrict__ w2, const float* __restrict__ w3,
                         const int* __restrict__ m,
                         __half* __restrict__ xp, __half* __restrict__ wp,
                         __nv_bfloat16* __restrict__ mb)
{
    int i = (blockIdx.x * 256 + threadIdx.x) * 4;
    int y = blockIdx.y;
    if (y == 0) {
        float4 a = *(const float4*)(x + i);
        uint2 o;
        o.x = packh2(a.x, a.y);
        o.y = packh2(a.z, a.w);
        *(uint2*)(xp + i) = o;
    } else if (y == 1) {
        int wsel = i >> 20;                   // which of 4 weights (1M each)
        int wi   = i & ((1 << 20) - 1);
        const float* src = (wsel == 0) ? w0 : (wsel == 1) ? w1
                         : (wsel == 2) ? w2 : w3;
        float4 a = *(const float4*)(src + wi);
        uint2 o;
        o.x = packh2(a.x, a.y);
        o.y = packh2(a.z, a.w);
        *(uint2*)(wp + i) = o;
    } else {
        int4 a = *(const int4*)(m + i);
        __nv_bfloat162 p0 = __floats2bfloat162_rn((float)(a.x - 1) * 1e9f,
                                                  (float)(a.y - 1) * 1e9f);
        __nv_bfloat162 p1 = __floats2bfloat162_rn((float)(a.z - 1) * 1e9f,
                                                  (float)(a.w - 1) * 1e9f);
        uint2 o;
        o.x = reinterpret_cast<uint32_t&>(p0);
        o.y = reinterpret_cast<uint32_t&>(p1);
        *(uint2*)(mb + i) = o;
    }
}

// ===========================================================================
// fp16 GEMM core (CTA 128x128, BK=64, 3-stage cp.async ring, 8 warps)
// ===========================================================================
#define BKP 72                     // padded K stride (fp16 elems), 144 B
#define ASZH (128 * BKP * 2)       // 18432 bytes per array
#define SSTG (2 * ASZH)            // 36864 per stage
#define GSMEM (3 * SSTG)           // 110592 (3-stage; 2 CTAs/SM = 221 KB)

__device__ __forceinline__ void gemm_core(
    const __half* __restrict__ A_g, const __half* __restrict__ B_g,
    uint32_t sb, int tid, float acc[4][4][4])
{
    const int lane = tid & 31;
    const int wid  = tid >> 5;
    const int wm   = (wid >> 2) * 64;
    const int wn   = (wid & 3) * 32;

    const __half* gsrc[2] = { A_g, B_g };

    const uint32_t a_off = ((wm + (lane & 15)) * BKP + (lane >> 4) * 8) * 2;
    // B pair-load via x4: 4 m8n8 matrices = two n8k16 fragments
    const uint32_t b_off4 = ((wn + (lane & 7) + ((lane >> 4) & 1) * 8) * BKP
                             + ((lane >> 3) & 1) * 8) * 2;

#pragma unroll
    for (int i = 0; i < 4; i++)
#pragma unroll
        for (int j = 0; j < 4; j++)
#pragma unroll
            for (int r = 0; r < 4; r++) acc[i][j][r] = 0.0f;

#define GLOAD(stg, kc) do {                                                  \
    uint32_t _sbase = sb + (stg) * SSTG;                                     \
    _Pragma("unroll")                                                        \
    for (int j = 0; j < 8; j++) {                                            \
        int arr = j >> 2;                                                    \
        int w   = tid + (j & 3) * 256;                                       \
        int row = w >> 3;                                                    \
        int c8  = (w & 7) * 8;                                               \
        cp16(_sbase + arr * ASZH + (uint32_t)(row * BKP + c8) * 2,           \
             gsrc[arr] + (size_t)row * 1024 + (kc) + c8);                    \
    } } while (0)

    GLOAD(0, 0);
    cp_commit();
    GLOAD(1, 64);
    cp_commit();

    int s_cur = 0, s_nxt = 2;
    for (int kc = 0; kc < 16; kc++) {
        if (kc < 15) cp_wait<1>(); else cp_wait<0>();
        __syncthreads();                     // sole barrier per chunk
        if (kc < 14) {
            GLOAD(s_nxt, (kc + 2) * 64);
            cp_commit();
        }

        const uint32_t sA = sb + s_cur * SSTG;
        const uint32_t sB = sA + ASZH;

#pragma unroll
        for (int ks = 0; ks < 4; ks++) {
            const uint32_t kb = ks * 32;

            uint32_t af[4][4];
#pragma unroll
            for (int tm = 0; tm < 4; tm++)
                ldm_x4(af[tm], sA + a_off + kb + tm * (16 * BKP * 2));

            uint32_t bfr[2][4];               // [pair][4 regs = 2 fragments]
#pragma unroll
            for (int p = 0; p < 2; p++)
                ldm_x4(bfr[p], sB + b_off4 + kb + p * (16 * BKP * 2));

#pragma unroll
            for (int tm = 0; tm < 4; tm++)
#pragma unroll
                for (int p = 0; p < 2; p++) {
                    mma_f16(acc[tm][2*p],   af[tm], &bfr[p][0]);
                    mma_f16(acc[tm][2*p+1], af[tm], &bfr[p][2]);
                }
        }
        s_cur = (s_cur == 2) ? 0 : s_cur + 1;
        s_nxt = (s_nxt == 2) ? 0 : s_nxt + 1;
    }
#undef GLOAD
}

// ---- fused QKV projection: grid (8, 32, 3) ----
__global__ __launch_bounds__(256, 2)
void gemm_qkv(const __half* __restrict__ X, const __half* __restrict__ W,
              const float* __restrict__ bq, const float* __restrict__ bk,
              const float* __restrict__ bv,
              __half* __restrict__ Q, __half* __restrict__ K,
              __half* __restrict__ V)
{
    extern __shared__ __align__(16) char smg[];
    const uint32_t sb = smem_u32(smg);
    const int tid = threadIdx.x;
    const int m0  = blockIdx.y * 128;
    const int n0  = blockIdx.x * 128;
    const int z   = blockIdx.z;

    const __half* Wz   = W + (size_t)z * NM * NM;
    const float*  bias = (z == 0) ? bq : (z == 1) ? bk : bv;
    __half*       Out  = (z == 0) ? Q  : (z == 1) ? K  : V;

    float acc[4][4][4];
    gemm_core(X + (size_t)m0 * 1024, Wz + (size_t)n0 * 1024, sb, tid, acc);

    const int lane = tid & 31;
    const int wid  = tid >> 5;
    const int wm   = (wid >> 2) * 64;
    const int wn   = (wid & 3) * 32;
    const int qr   = lane >> 2;
    const int qc   = (lane & 3) * 2;
#pragma unroll
    for (int tm = 0; tm < 4; tm++) {
        int row = m0 + wm + tm * 16 + qr;
#pragma unroll
        for (int tn = 0; tn < 4; tn++) {
            int col = n0 + wn + tn * 8 + qc;
            float b0 = bias[col], b1 = bias[col + 1];
            *(uint32_t*)(Out + (size_t)row * 1024 + col) =
                packh2(acc[tm][tn][0] + b0, acc[tm][tn][1] + b1);
            *(uint32_t*)(Out + (size_t)(row + 8) * 1024 + col) =
                packh2(acc[tm][tn][2] + b0, acc[tm][tn][3] + b1);
        }
    }
}

// ---- output projection (fp32 out) ----
__global__ __launch_bounds__(256, 2)
void gemm_o(const __half* __restrict__ A_g, const __half* __restrict__ B_g,
            const float* __restrict__ bias, float* __restrict__ Cf)
{
    extern __shared__ __align__(16) char smg[];
    const uint32_t sb = smem_u32(smg);
    const int tid = threadIdx.x;
    const int m0  = blockIdx.y * 128;
    const int n0  = blockIdx.x * 128;

    float acc[4][4][4];
    gemm_core(A_g + (size_t)m0 * 1024, B_g + (size_t)n0 * 1024, sb, tid, acc);

    const int lane = tid & 31;
    const int wid  = tid >> 5;
    const int wm   = (wid >> 2) * 64;
    const int wn   = (wid & 3) * 32;
    const int qr   = lane >> 2;
    const int qc   = (lane & 3) * 2;
#pragma unroll
    for (int tm = 0; tm < 4; tm++) {
        int row = m0 + wm + tm * 16 + qr;
#pragma unroll
        for (int tn = 0; tn < 4; tn++) {
            int col = n0 + wn + tn * 8 + qc;
            float b0 = bias[col], b1 = bias[col + 1];
            *(float2*)(Cf + (size_t)row * 1024 + col) =
                make_float2(acc[tm][tn][0] + b0, acc[tm][tn][1] + b1);
            *(float2*)(Cf + (size_t)(row + 8) * 1024 + col) =
                make_float2(acc[tm][tn][2] + b0, acc[tm][tn][3] + b1);
        }
    }
}

// ===========================================================================
// fp16 flash attention with double-buffered K/V (unchanged from R8)
// ===========================================================================
#define ALD 72
#define ABUF (128 * ALD * 2)   // 18432 bytes per buffer

__global__ __launch_bounds__(256)
void attn_h(const __half* __restrict__ q, const __half* __restrict__ k,
            const __half* __restrict__ v, const __nv_bfloat16* __restrict__ mb,
            __half* __restrict__ ctx)
{
    extern __shared__ __align__(16) char sma[];
    const uint32_t sQ  = smem_u32(sma);
    const uint32_t sK0 = sQ + ABUF;
    const uint32_t sV0 = sQ + 2 * ABUF;
    const uint32_t sK1 = sQ + 3 * ABUF;
    const uint32_t sV1 = sQ + 4 * ABUF;

    const int tid  = threadIdx.x;
    const int lane = tid & 31;
    const int wid  = tid >> 5;
    const int q0   = blockIdx.x * 128;
    const int h    = blockIdx.y;
    const int b    = blockIdx.z;

    const size_t base  = (size_t)b * SEQ * NM + (size_t)h * ND;
    const size_t mbase = (size_t)b * SEQ * SEQ;

    const __half* ksrc = k + base;
    const __half* vsrc = v + base;

#define KVLOAD(kbuf, vbuf, k0) do {                                          \
    _Pragma("unroll")                                                        \
    for (int j = 0; j < 8; j++) {                                            \
        int arr = j >> 2;                                                    \
        int w   = tid + (j & 3) * 256;                                       \
        int row = w >> 3;                                                    \
        int c8  = (w & 7) * 8;                                               \
        cp16((arr ? (vbuf) : (kbuf)) + (uint32_t)(row * ALD + c8) * 2,       \
             (arr ? vsrc : ksrc) + (size_t)((k0) + row) * 1024 + c8);        \
    }                                                                        \
    cp_commit(); } while (0)

#pragma unroll
    for (int j = 0; j < 4; j++) {
        int w   = tid + j * 256;
        int row = w >> 3;
        int c8  = (w & 7) * 8;
        cp16(sQ + (uint32_t)(row * ALD + c8) * 2,
             q + base + (size_t)(q0 + row) * 1024 + c8);
    }
    cp_commit();
    KVLOAD(sK0, sV0, 0);

    cp_wait<1>();
    __syncthreads();

    uint32_t qf[4][4];
    {
        uint32_t qo = ((wid * 16 + (lane & 15)) * ALD + (lane >> 4) * 8) * 2;
#pragma unroll
        for (int ks = 0; ks < 4; ks++)
            ldm_x4(qf[ks], sQ + qo + ks * 32);
    }

    float oacc[8][4];
#pragma unroll
    for (int i = 0; i < 8; i++)
#pragma unroll
        for (int r = 0; r < 4; r++) oacc[i][r] = 0.0f;
    float mr1 = -INFINITY, mr2 = -INFINITY, lr1 = 0.0f, lr2 = 0.0f;

    const float SCALE = 0.03125f;
    const int r1 = wid * 16 + (lane >> 2);

    const uint32_t koff = ((lane & 7) * ALD + ((lane >> 3) & 3) * 8) * 2;
    const uint32_t voff = (((lane & 7) + 8 * ((lane >> 3) & 1)) * ALD) * 2
                        + ((lane >> 4) & 1) * 16;

    for (int t = 0; t < 8; t++) {
        cp_wait<0>();
        __syncthreads();

        const uint32_t sK = (t & 1) ? sK1 : sK0;
        const uint32_t sV = (t & 1) ? sV1 : sV0;
        if (t < 7) {
            if (t & 1) KVLOAD(sK0, sV0, (t + 1) * 128);
            else       KVLOAD(sK1, sV1, (t + 1) * 128);
        }
        const int k0 = t * 128;

        float sacc[16][4];
#pragma unroll
        for (int j = 0; j < 16; j++) {
#pragma unroll
            for (int r = 0; r < 4; r++) sacc[j][r] = 0.0f;
            uint32_t ka = koff + (uint32_t)(j * 8 * ALD * 2);
            uint32_t kf[8];
            ldm_x4(kf,     sK + ka);
            ldm_x4(kf + 4, sK + ka + 64);
#pragma unroll
            for (int ks = 0; ks < 4; ks++)
                mma_f16(sacc[j], qf[ks], &kf[ks * 2]);
        }

        const __nv_bfloat16* mp =
            mb + mbase + (size_t)(q0 + r1) * SEQ + k0 + (lane & 3) * 2;
        float rmax1 = -INFINITY, rmax2 = -INFINITY;
#pragma unroll
        for (int j = 0; j < 16; j++) {
            uint32_t ma = *(const uint32_t*)(mp + j * 8);
            uint32_t mc = *(const uint32_t*)(mp + 8 * SEQ + j * 8);
            float2 f1 = __bfloat1622float2(reinterpret_cast<__nv_bfloat162&>(ma));
            float2 f2 = __bfloat1622float2(reinterpret_cast<__nv_bfloat162&>(mc));
            sacc[j][0] = sacc[j][0] * SCALE + f1.x;
            sacc[j][1] = sacc[j][1] * SCALE + f1.y;
            sacc[j][2] = sacc[j][2] * SCALE + f2.x;
            sacc[j][3] = sacc[j][3] * SCALE + f2.y;
            rmax1 = fmaxf(rmax1, fmaxf(sacc[j][0], sacc[j][1]));
            rmax2 = fmaxf(rmax2, fmaxf(sacc[j][2], sacc[j][3]));
        }
#pragma unroll
        for (int off = 1; off < 4; off <<= 1) {
            rmax1 = fmaxf(rmax1, __shfl_xor_sync(0xffffffffu, rmax1, off));
            rmax2 = fmaxf(rmax2, __shfl_xor_sync(0xffffffffu, rmax2, off));
        }

        float mn1 = fmaxf(mr1, rmax1);
        float mn2 = fmaxf(mr2, rmax2);
        float c1 = __expf(mr1 - mn1);
        float c2 = __expf(mr2 - mn2);
        mr1 = mn1; mr2 = mn2;
#pragma unroll
        for (int i = 0; i < 8; i++) {
            oacc[i][0] *= c1; oacc[i][1] *= c1;
            oacc[i][2] *= c2; oacc[i][3] *= c2;
        }
        float rs1 = 0.0f, rs2 = 0.0f;
#pragma unroll
        for (int j = 0; j < 16; j++) {
            sacc[j][0] = __expf(sacc[j][0] - mn1);
            sacc[j][1] = __expf(sacc[j][1] - mn1);
            sacc[j][2] = __expf(sacc[j][2] - mn2);
            sacc[j][3] = __expf(sacc[j][3] - mn2);
            rs1 += sacc[j][0] + sacc[j][1];
            rs2 += sacc[j][2] + sacc[j][3];
        }
#pragma unroll
        for (int off = 1; off < 4; off <<= 1) {
            rs1 += __shfl_xor_sync(0xffffffffu, rs1, off);
            rs2 += __shfl_xor_sync(0xffffffffu, rs2, off);
        }
        lr1 = lr1 * c1 + rs1;
        lr2 = lr2 * c2 + rs2;

#pragma unroll
        for (int ks = 0; ks < 8; ks++) {
            uint32_t ph[4];
            ph[0] = packh2(sacc[2*ks][0],   sacc[2*ks][1]);
            ph[1] = packh2(sacc[2*ks][2],   sacc[2*ks][3]);
            ph[2] = packh2(sacc[2*ks+1][0], sacc[2*ks+1][1]);
            ph[3] = packh2(sacc[2*ks+1][2], sacc[2*ks+1][3]);

            uint32_t va = voff + (uint32_t)(ks * 16 * ALD * 2);
#pragma unroll
            for (int tp = 0; tp < 4; tp++) {
                uint32_t vf[4];
                ldm_x4t(vf, sV + va + tp * 32);
                mma_f16(oacc[2*tp],   ph, &vf[0]);
                mma_f16(oacc[2*tp+1], ph, &vf[2]);
            }
        }
    }
#undef KVLOAD

    float i1 = 1.0f / lr1, i2 = 1.0f / lr2;
    size_t off0 = base + (size_t)(q0 + r1) * NM + (lane & 3) * 2;
#pragma unroll
    for (int tn = 0; tn < 8; tn++) {
        *(uint32_t*)(ctx + off0 + tn * 8) =
            packh2(oacc[tn][0] * i1, oacc[tn][1] * i1);
        *(uint32_t*)(ctx + off0 + 8 * NM + tn * 8) =
            packh2(oacc[tn][2] * i2, oacc[tn][3] * i2);
    }
}

// ---------------------------------------------------------------------------
// kernel_launch — inputs: x, mask, Wq, bq, Wk, bk, Wv, bv, Wo, bo
// ---------------------------------------------------------------------------
extern "C" void kernel_launch(void* const* d_in, const int* in_sizes, int n_in,
                              void* d_out, int out_size)
{
    const float* x    = (const float*)d_in[0];
    const int*   mask = (const int*)  d_in[1];
    const float* Wq   = (const float*)d_in[2];
    const float* bq   = (const float*)d_in[3];
    const float* Wk   = (const float*)d_in[4];
    const float* bk   = (const float*)d_in[5];
    const float* Wv   = (const float*)d_in[6];
    const float* bv   = (const float*)d_in[7];
    const float* Wo   = (const float*)d_in[8];
    const float* bo   = (const float*)d_in[9];
    float* out = (float*)d_out;

    __half *xp, *wp, *qp, *kp, *vp, *cp;
    __nv_bfloat16* mbp;
    cudaGetSymbolAddress((void**)&xp, g_x);
    cudaGetSymbolAddress((void**)&wp, g_w);
    cudaGetSymbolAddress((void**)&qp, g_q);
    cudaGetSymbolAddress((void**)&kp, g_k);
    cudaGetSymbolAddress((void**)&vp, g_v);
    cudaGetSymbolAddress((void**)&cp, g_c);
    cudaGetSymbolAddress((void**)&mbp, g_mb);

    // ---- conversions (one launch) ----
    dim3 cgrid(ROWS * NM / 1024, 3);
    conv_all<<<cgrid, 256>>>(x, Wq, Wk, Wv, Wo, mask, xp, wp, mbp);

    // ---- fused QKV projection ----
    cudaFuncSetAttribute(gemm_qkv,
                         cudaFuncAttributeMaxDynamicSharedMemorySize, GSMEM);
    cudaFuncSetAttribute(gemm_o,
                         cudaFuncAttributeMaxDynamicSharedMemorySize, GSMEM);
    dim3 gblock(256);
    dim3 qgrid(NM / 128, ROWS / 128, 3);   // (8, 32, 3)
    gemm_qkv<<<qgrid, gblock, GSMEM>>>(xp, wp, bq, bk, bv, qp, kp, vp);

    // ---- attention ----
    const int asmem = 5 * ABUF;   // 92160
    cudaFuncSetAttribute(attn_h,
                         cudaFuncAttributeMaxDynamicSharedMemorySize, asmem);
    dim3 agrid(SEQ / 128, NH, BATCH);
    attn_h<<<agrid, 256, asmem>>>(qp, kp, vp, mbp, cp);

    // ---- output projection ----
    dim3 ogrid(NM / 128, ROWS / 128);
    gemm_o<<<ogrid, gblock, GSMEM>>>(cp, wp + 3 * (size_t)NM * NM, bo, out);
}